// round 1
// baseline (speedup 1.0000x reference)
#include <cuda_runtime.h>
#include <cuda_bf16.h>
#include <math.h>

// Problem constants
#define BATCH   2
#define SEQ     8192
#define DMODEL  1024
#define NHEADS  16
#define HDIM    64
#define SEGLEN  2048
#define DILAT   2
#define NSEG    4            // SEQ / SEGLEN
#define LSEG    1024         // SEGLEN / DILAT
#define MROWS   8192         // BATCH * NSEG * LSEG
#define DQKV    3072         // 3 * DMODEL

// Scratch (device globals: allocation-free per harness rules)
__device__ float g_qkv[(size_t)MROWS * DQKV];    // 96 MB
__device__ float g_attn[(size_t)MROWS * DMODEL]; // 32 MB

// ---------------------------------------------------------------------------
// Tiled fp32 SGEMM: C[M x Ncols] = A[M x 1024] * B[1024 x Ncols] + bias
// 128x128 block tile, BK=8, 256 threads, 8x8 per-thread register tile.
// GATHER=true applies the dilated row gather on A (A = x, stride DMODEL).
// ---------------------------------------------------------------------------
template<bool GATHER>
__global__ void __launch_bounds__(256)
sgemm128(const float* __restrict__ A, const float* __restrict__ Bmat,
         const float* __restrict__ bias, float* __restrict__ C,
         int K, int Ncols)
{
    __shared__ float As[8][128];
    __shared__ float Bs[8][128];

    const int tid = threadIdx.x;
    const int bm = blockIdx.y * 128;
    const int bn = blockIdx.x * 128;

    // A tile load mapping: 128 rows x 8 k's; each thread loads one float4
    const int arow = tid >> 1;
    const int acol = (tid & 1) * 4;
    long asrc;
    if (GATHER) {
        int m   = bm + arow;
        int b   = m >> 12;          // / 4096
        int rem = m & 4095;
        int n   = rem >> 10;        // / 1024
        int l   = rem & 1023;
        asrc = ((long)(b * SEQ + n * SEGLEN + DILAT * l)) * (long)K;
    } else {
        asrc = (long)(bm + arow) * (long)K;
    }

    // B tile load mapping: 8 k-rows x 128 cols; each thread loads one float4
    const int brow = tid >> 5;
    const int bcol = (tid & 31) * 4;
    const float* Bp = Bmat + (long)brow * Ncols + bn + bcol;

    const int tx = tid & 15;   // 16 col-threads
    const int ty = tid >> 4;   // 16 row-threads

    float acc[8][8];
#pragma unroll
    for (int i = 0; i < 8; i++)
#pragma unroll
        for (int j = 0; j < 8; j++) acc[i][j] = 0.f;

#pragma unroll 1
    for (int k0 = 0; k0 < K; k0 += 8) {
        float4 av = *(const float4*)(A + asrc + k0 + acol);
        float4 bv = *(const float4*)(Bp + (long)k0 * Ncols);
        __syncthreads();
        As[acol + 0][arow] = av.x;
        As[acol + 1][arow] = av.y;
        As[acol + 2][arow] = av.z;
        As[acol + 3][arow] = av.w;
        *(float4*)&Bs[brow][bcol] = bv;
        __syncthreads();

#pragma unroll
        for (int k = 0; k < 8; k++) {
            float a[8], b[8];
            *(float4*)(a)     = *(const float4*)&As[k][ty * 8];
            *(float4*)(a + 4) = *(const float4*)&As[k][ty * 8 + 4];
            *(float4*)(b)     = *(const float4*)&Bs[k][tx * 8];
            *(float4*)(b + 4) = *(const float4*)&Bs[k][tx * 8 + 4];
#pragma unroll
            for (int i = 0; i < 8; i++)
#pragma unroll
                for (int j = 0; j < 8; j++)
                    acc[i][j] += a[i] * b[j];
        }
    }

    // Epilogue with bias
#pragma unroll
    for (int i = 0; i < 8; i++) {
        int row = bm + ty * 8 + i;
        float* Cp = C + (long)row * Ncols + bn + tx * 8;
#pragma unroll
        for (int j = 0; j < 8; j += 4) {
            float4 o;
            o.x = acc[i][j + 0] + bias[bn + tx * 8 + j + 0];
            o.y = acc[i][j + 1] + bias[bn + tx * 8 + j + 1];
            o.z = acc[i][j + 2] + bias[bn + tx * 8 + j + 2];
            o.w = acc[i][j + 3] + bias[bn + tx * 8 + j + 3];
            *(float4*)(Cp + j) = o;
        }
    }
}

// ---------------------------------------------------------------------------
// Flash attention, fp32. One block = (b*n, head, 128-query tile).
// 128 threads, one query per thread; K/V processed in 32-key smem tiles.
// qkv layout: [MROWS x 3072]; q cols [0,1024), k [1024,2048), v [2048,3072);
// head h occupies cols h*64 .. h*64+64 within each third.
// ---------------------------------------------------------------------------
__global__ void __launch_bounds__(128)
attn_kernel(const float* __restrict__ qkv, float* __restrict__ outp)
{
    __shared__ float Qs[64][128];   // transposed: [d][query]  (32 KB)
    __shared__ float Ks[32][64];    // 8 KB
    __shared__ float Vs[32][64];    // 8 KB

    const int tid = threadIdx.x;
    const int qt  = blockIdx.x & 7;          // 8 query tiles of 128
    const int h   = (blockIdx.x >> 3) & 15;  // head
    const int bn  = blockIdx.x >> 7;         // 0..7 = b*NSEG + n
    const long rowbase = (long)bn * LSEG;

    const float* Qg = qkv + (rowbase + qt * 128) * DQKV + h * HDIM;
    const float* Kg = qkv + rowbase * DQKV + DMODEL     + h * HDIM;
    const float* Vg = qkv + rowbase * DQKV + 2 * DMODEL + h * HDIM;

    // Load this tile's 128x64 Q, transposed into smem (each thread = own row)
#pragma unroll
    for (int c4 = 0; c4 < 16; c4++) {
        float4 v = *(const float4*)(Qg + (long)tid * DQKV + c4 * 4);
        Qs[c4 * 4 + 0][tid] = v.x;
        Qs[c4 * 4 + 1][tid] = v.y;
        Qs[c4 * 4 + 2][tid] = v.z;
        Qs[c4 * 4 + 3][tid] = v.w;
    }

    float acc[64];
#pragma unroll
    for (int d = 0; d < 64; d++) acc[d] = 0.f;
    float mi = -1e30f;
    float li = 0.f;

#pragma unroll 1
    for (int kt = 0; kt < 32; kt++) {
        __syncthreads();
        // Cooperative load of 32x64 K and V tiles
#pragma unroll
        for (int it = 0; it < 4; it++) {
            int i = tid + it * 128;          // 0..511
            int r = i >> 4;                  // key row 0..31
            int c = i & 15;                  // float4 col
            long g = (long)(kt * 32 + r) * DQKV + c * 4;
            *(float4*)&Ks[r][c * 4] = *(const float4*)(Kg + g);
            *(float4*)&Vs[r][c * 4] = *(const float4*)(Vg + g);
        }
        __syncthreads();

        // Scores for my query vs 32 keys
        float s[32];
#pragma unroll
        for (int kk = 0; kk < 32; kk++) s[kk] = 0.f;
#pragma unroll 1
        for (int d4 = 0; d4 < 16; d4++) {
            float q0 = Qs[d4 * 4 + 0][tid];
            float q1 = Qs[d4 * 4 + 1][tid];
            float q2 = Qs[d4 * 4 + 2][tid];
            float q3 = Qs[d4 * 4 + 3][tid];
#pragma unroll
            for (int kk = 0; kk < 32; kk++) {
                float4 k4 = *(const float4*)&Ks[kk][d4 * 4];
                s[kk] += q0 * k4.x + q1 * k4.y + q2 * k4.z + q3 * k4.w;
            }
        }

        // Online softmax update
        const float SCALE = 0.125f;  // 1/sqrt(64)
        float tmax = mi;
#pragma unroll
        for (int kk = 0; kk < 32; kk++) {
            s[kk] *= SCALE;
            tmax = fmaxf(tmax, s[kk]);
        }
        float corr = __expf(mi - tmax);
        mi = tmax;
        li *= corr;
#pragma unroll
        for (int d = 0; d < 64; d++) acc[d] *= corr;

#pragma unroll 1
        for (int kk = 0; kk < 32; kk++) {
            float p = __expf(s[kk] - mi);
            li += p;
#pragma unroll
            for (int d4 = 0; d4 < 16; d4++) {
                float4 v4 = *(const float4*)&Vs[kk][d4 * 4];
                acc[d4 * 4 + 0] += p * v4.x;
                acc[d4 * 4 + 1] += p * v4.y;
                acc[d4 * 4 + 2] += p * v4.z;
                acc[d4 * 4 + 3] += p * v4.w;
            }
        }
    }

    const float inv = 1.f / li;
    float* Op = outp + (rowbase + qt * 128 + tid) * DMODEL + h * HDIM;
#pragma unroll
    for (int d4 = 0; d4 < 16; d4++) {
        float4 o;
        o.x = acc[d4 * 4 + 0] * inv;
        o.y = acc[d4 * 4 + 1] * inv;
        o.z = acc[d4 * 4 + 2] * inv;
        o.w = acc[d4 * 4 + 3] * inv;
        *(float4*)(Op + d4 * 4) = o;
    }
}

// ---------------------------------------------------------------------------
extern "C" void kernel_launch(void* const* d_in, const int* in_sizes, int n_in,
                              void* d_out, int out_size)
{
    const float* x    = (const float*)d_in[0];
    const float* wqkv = (const float*)d_in[1];
    const float* bqkv = (const float*)d_in[2];
    const float* wo   = (const float*)d_in[3];
    const float* bo   = (const float*)d_in[4];
    float* out = (float*)d_out;

    float *qkv_ptr, *attn_ptr;
    cudaGetSymbolAddress((void**)&qkv_ptr, g_qkv);
    cudaGetSymbolAddress((void**)&attn_ptr, g_attn);

    // 1) Fused QKV projection with dilated gather: [8192 x 3072]
    dim3 g1(DQKV / 128, MROWS / 128);
    sgemm128<true><<<g1, 256>>>(x, wqkv, bqkv, qkv_ptr, DMODEL, DQKV);

    // 2) Per-segment per-head attention: 8 bn * 16 heads * 8 qtiles = 1024 blocks
    attn_kernel<<<1024, 128>>>(qkv_ptr, attn_ptr);

    // 3) Output projection: [8192 x 1024]
    dim3 g3(DMODEL / 128, MROWS / 128);
    sgemm128<false><<<g3, 256>>>(attn_ptr, wo, bo, out, DMODEL, DMODEL);
}

// round 3
// speedup vs baseline: 1.4675x; 1.4675x over previous
#include <cuda_runtime.h>
#include <cuda_bf16.h>
#include <cstdint>
#include <math.h>

// Problem constants
#define BATCH   2
#define SEQ     8192
#define DMODEL  1024
#define NHEADS  16
#define HDIM    64
#define SEGLEN  2048
#define LSEG    1024
#define MROWS   8192
#define DQKV    3072

// ---------------- device scratch (allocation-free) ----------------
__device__ float          g_qkv[(size_t)MROWS * DQKV];
__device__ __nv_bfloat16  g_xhi[(size_t)MROWS * DMODEL];
__device__ __nv_bfloat16  g_xlo[(size_t)MROWS * DMODEL];
__device__ __nv_bfloat16  g_wqh[(size_t)DQKV * DMODEL];   // wqkv^T [N x K]
__device__ __nv_bfloat16  g_wql[(size_t)DQKV * DMODEL];
__device__ __nv_bfloat16  g_woh[(size_t)DMODEL * DMODEL];
__device__ __nv_bfloat16  g_wol[(size_t)DMODEL * DMODEL];
__device__ __nv_bfloat16  g_ohi[(size_t)MROWS * DMODEL];
__device__ __nv_bfloat16  g_olo[(size_t)MROWS * DMODEL];

// ---------------- PTX helpers (sm_103-legal: mma.sync / ldmatrix / cp.async) --
__device__ __forceinline__ uint32_t smem_u32(const void* p) {
    uint32_t a;
    asm("{ .reg .u64 t; cvta.to.shared.u64 t, %1; cvt.u32.u64 %0, t; }" : "=r"(a) : "l"(p));
    return a;
}
__device__ __forceinline__ void cp16(uint32_t s, const void* g) {
    asm volatile("cp.async.cg.shared.global [%0], [%1], 16;" :: "r"(s), "l"(g));
}
__device__ __forceinline__ void cp_commit() {
    asm volatile("cp.async.commit_group;");
}
__device__ __forceinline__ void cp_wait1() {
    asm volatile("cp.async.wait_group 1;");
}
__device__ __forceinline__ void cp_wait0() {
    asm volatile("cp.async.wait_group 0;");
}
__device__ __forceinline__ void ldm4(uint32_t* r, uint32_t addr) {
    asm volatile("ldmatrix.sync.aligned.m8n8.x4.shared.b16 {%0,%1,%2,%3}, [%4];"
        : "=r"(r[0]), "=r"(r[1]), "=r"(r[2]), "=r"(r[3]) : "r"(addr));
}
__device__ __forceinline__ void mma16816(float* c, const uint32_t* a, const uint32_t* b) {
    asm volatile(
        "mma.sync.aligned.m16n8k16.row.col.f32.bf16.bf16.f32 "
        "{%0,%1,%2,%3}, {%4,%5,%6,%7}, {%8,%9}, {%0,%1,%2,%3};"
        : "+f"(c[0]), "+f"(c[1]), "+f"(c[2]), "+f"(c[3])
        : "r"(a[0]), "r"(a[1]), "r"(a[2]), "r"(a[3]), "r"(b[0]), "r"(b[1]));
}

// ---------------------------------------------------------------------------
// convert+gather x -> bf16 hi/lo
// ---------------------------------------------------------------------------
__global__ void __launch_bounds__(256) conv_x(const float* __restrict__ x) {
    int m = blockIdx.x;
    int b = m >> 12, rem = m & 4095, n = rem >> 10, l = rem & 1023;
    const float* src = x + ((size_t)(b * SEQ + n * SEGLEN + 2 * l)) * DMODEL;
    size_t dst = (size_t)m * DMODEL + threadIdx.x * 4;
    float4 v = *(const float4*)(src + threadIdx.x * 4);
    float vv[4] = {v.x, v.y, v.z, v.w};
    __nv_bfloat16 h[4], lo[4];
#pragma unroll
    for (int i = 0; i < 4; i++) {
        h[i] = __float2bfloat16(vv[i]);
        lo[i] = __float2bfloat16(vv[i] - __bfloat162float(h[i]));
    }
    *(uint2*)(g_xhi + dst) = *(uint2*)h;
    *(uint2*)(g_xlo + dst) = *(uint2*)lo;
}

// ---------------------------------------------------------------------------
// weight transpose + convert: W[K x N] fp32 -> B[N x K] bf16 hi/lo
// ---------------------------------------------------------------------------
__global__ void __launch_bounds__(256)
wconv(const float* __restrict__ W, __nv_bfloat16* __restrict__ Bh,
      __nv_bfloat16* __restrict__ Bl, int K, int N) {
    __shared__ float t[32][33];
    int n0 = blockIdx.x * 32, k0 = blockIdx.y * 32;
    int tx = threadIdx.x, ty = threadIdx.y;
    for (int i = ty; i < 32; i += 8)
        t[i][tx] = W[(size_t)(k0 + i) * N + n0 + tx];
    __syncthreads();
    for (int i = ty; i < 32; i += 8) {
        float v = t[tx][i];
        __nv_bfloat16 h = __float2bfloat16(v);
        __nv_bfloat16 lo = __float2bfloat16(v - __bfloat162float(h));
        size_t o = (size_t)(n0 + i) * K + k0 + tx;
        Bh[o] = h;
        Bl[o] = lo;
    }
}

// ---------------------------------------------------------------------------
// HMMA GEMM: C[M x N] = A[M x 1024](hi+lo) * B[N x 1024]^T(hi+lo) + bias
// 128x128 tile, BK=32, 256 thr (8 warps, 32x64 warp tile), cp.async dbl-buffer.
// smem row stride 40 elems (80B) -> conflict-free ldmatrix phases.
// ---------------------------------------------------------------------------
#define TS      10240                 // 128 rows * 40 elem * 2B per tile
#define SMEM_DYN (8 * TS)             // 4 tiles x 2 stages = 80KB

__global__ void __launch_bounds__(256)
gemm_mma(const __nv_bfloat16* __restrict__ Ah, const __nv_bfloat16* __restrict__ Al,
         const __nv_bfloat16* __restrict__ Bh, const __nv_bfloat16* __restrict__ Bl,
         const float* __restrict__ bias, float* __restrict__ C, int Ncols)
{
    extern __shared__ char dsm[];
    __shared__ float biass[128];

    const int tid  = threadIdx.x;
    const int wid  = tid >> 5, lane = tid & 31;
    const int wm   = wid & 3, wn = wid >> 2;          // 4x2 warp grid
    const int bn   = blockIdx.x * 128, bm = blockIdx.y * 128;
    const uint32_t sb = smem_u32(dsm);

    if (tid < 128) biass[tid] = bias[bn + tid];

    const __nv_bfloat16* srcs[4] = {
        Ah + (size_t)bm * DMODEL, Al + (size_t)bm * DMODEL,
        Bh + (size_t)bn * DMODEL, Bl + (size_t)bn * DMODEL };

    // per-thread cp.async mapping (8 chunks of 16B)
    int crow[8], ckc[8], ctile[8];
#pragma unroll
    for (int i = 0; i < 8; i++) {
        int c = tid + i * 256;
        ctile[i] = c >> 9;
        crow[i]  = (c >> 2) & 127;
        ckc[i]   = (c & 3) * 8;
    }

    // ldmatrix per-thread byte offsets (within a tile)
    uint32_t aRow[2], bRow[4];
#pragma unroll
    for (int mt = 0; mt < 2; mt++)
        aRow[mt] = (uint32_t)((wm * 32 + mt * 16 + (lane & 15)) * 80 + (lane >> 4) * 16);
#pragma unroll
    for (int nt2 = 0; nt2 < 4; nt2++)
        bRow[nt2] = (uint32_t)((wn * 64 + nt2 * 16 + (lane & 7) + ((lane >> 4) << 3)) * 80
                               + ((lane >> 3) & 1) * 16);

    float acc[2][8][4];
#pragma unroll
    for (int mt = 0; mt < 2; mt++)
#pragma unroll
        for (int nt = 0; nt < 8; nt++)
#pragma unroll
            for (int j = 0; j < 4; j++) acc[mt][nt][j] = 0.f;

    // prefetch stage 0
    {
        uint32_t sbase = sb;
#pragma unroll
        for (int i = 0; i < 8; i++)
            cp16(sbase + ctile[i] * TS + (crow[i] * 40 + ckc[i]) * 2,
                 srcs[ctile[i]] + (size_t)crow[i] * DMODEL + ckc[i]);
        cp_commit();
    }

    const int NK = DMODEL / 32;    // 32 chunks
#pragma unroll 1
    for (int kc = 0; kc < NK; kc++) {
        int cur = kc & 1;
        if (kc + 1 < NK) {
            uint32_t sbase = sb + (cur ^ 1) * 4 * TS;
            int k0 = (kc + 1) * 32;
#pragma unroll
            for (int i = 0; i < 8; i++)
                cp16(sbase + ctile[i] * TS + (crow[i] * 40 + ckc[i]) * 2,
                     srcs[ctile[i]] + (size_t)crow[i] * DMODEL + k0 + ckc[i]);
            cp_commit();
            cp_wait1();
        } else {
            cp_wait0();
        }
        __syncthreads();

        uint32_t tb = sb + cur * 4 * TS;
#pragma unroll
        for (int ks = 0; ks < 2; ks++) {
            uint32_t ko = ks * 32;          // 16 elems = 32B
            uint32_t ah[2][4], al[2][4], bh[4][4], bl[4][4];
#pragma unroll
            for (int mt = 0; mt < 2; mt++) {
                ldm4(ah[mt], tb + aRow[mt] + ko);
                ldm4(al[mt], tb + TS + aRow[mt] + ko);
            }
#pragma unroll
            for (int nt2 = 0; nt2 < 4; nt2++) {
                ldm4(bh[nt2], tb + 2 * TS + bRow[nt2] + ko);
                ldm4(bl[nt2], tb + 3 * TS + bRow[nt2] + ko);
            }
#pragma unroll
            for (int mt = 0; mt < 2; mt++)
#pragma unroll
                for (int nt = 0; nt < 8; nt++) {
                    int nt2 = nt >> 1, off = (nt & 1) * 2;
                    mma16816(acc[mt][nt], ah[mt], &bh[nt2][off]);
                    mma16816(acc[mt][nt], ah[mt], &bl[nt2][off]);
                    mma16816(acc[mt][nt], al[mt], &bh[nt2][off]);
                }
        }
        __syncthreads();
    }

    // epilogue
    const int gq = lane >> 2, t4 = lane & 3;
#pragma unroll
    for (int mt = 0; mt < 2; mt++) {
        int row0 = bm + wm * 32 + mt * 16 + gq;
#pragma unroll
        for (int nt = 0; nt < 8; nt++) {
            int colL = wn * 64 + nt * 8 + t4 * 2;
            int col  = bn + colL;
            float2 v0, v1;
            v0.x = acc[mt][nt][0] + biass[colL];
            v0.y = acc[mt][nt][1] + biass[colL + 1];
            v1.x = acc[mt][nt][2] + biass[colL];
            v1.y = acc[mt][nt][3] + biass[colL + 1];
            *(float2*)(C + (size_t)row0 * Ncols + col) = v0;
            *(float2*)(C + (size_t)(row0 + 8) * Ncols + col) = v1;
        }
    }
}

// ---------------------------------------------------------------------------
// Flash attention, fp32; epilogue emits bf16 hi/lo
// ---------------------------------------------------------------------------
__global__ void __launch_bounds__(128)
attn_kernel(const float* __restrict__ qkv)
{
    __shared__ float Qs[64][128];
    __shared__ float Ks[32][64];
    __shared__ float Vs[32][64];

    const int tid = threadIdx.x;
    const int qt  = blockIdx.x & 7;
    const int h   = (blockIdx.x >> 3) & 15;
    const int bn  = blockIdx.x >> 7;
    const long rowbase = (long)bn * LSEG;

    const float* Qg = qkv + (rowbase + qt * 128) * DQKV + h * HDIM;
    const float* Kg = qkv + rowbase * DQKV + DMODEL     + h * HDIM;
    const float* Vg = qkv + rowbase * DQKV + 2 * DMODEL + h * HDIM;

#pragma unroll
    for (int c4 = 0; c4 < 16; c4++) {
        float4 v = *(const float4*)(Qg + (long)tid * DQKV + c4 * 4);
        Qs[c4 * 4 + 0][tid] = v.x;
        Qs[c4 * 4 + 1][tid] = v.y;
        Qs[c4 * 4 + 2][tid] = v.z;
        Qs[c4 * 4 + 3][tid] = v.w;
    }

    float acc[64];
#pragma unroll
    for (int d = 0; d < 64; d++) acc[d] = 0.f;
    float mi = -1e30f;
    float li = 0.f;

#pragma unroll 1
    for (int kt = 0; kt < 32; kt++) {
        __syncthreads();
#pragma unroll
        for (int it = 0; it < 4; it++) {
            int i = tid + it * 128;
            int r = i >> 4;
            int c = i & 15;
            long g = (long)(kt * 32 + r) * DQKV + c * 4;
            *(float4*)&Ks[r][c * 4] = *(const float4*)(Kg + g);
            *(float4*)&Vs[r][c * 4] = *(const float4*)(Vg + g);
        }
        __syncthreads();

        float s[32];
#pragma unroll
        for (int kk = 0; kk < 32; kk++) s[kk] = 0.f;
#pragma unroll 1
        for (int d4 = 0; d4 < 16; d4++) {
            float q0 = Qs[d4 * 4 + 0][tid];
            float q1 = Qs[d4 * 4 + 1][tid];
            float q2 = Qs[d4 * 4 + 2][tid];
            float q3 = Qs[d4 * 4 + 3][tid];
#pragma unroll
            for (int kk = 0; kk < 32; kk++) {
                float4 k4 = *(const float4*)&Ks[kk][d4 * 4];
                s[kk] += q0 * k4.x + q1 * k4.y + q2 * k4.z + q3 * k4.w;
            }
        }

        const float SCALE = 0.125f;
        float tmax = mi;
#pragma unroll
        for (int kk = 0; kk < 32; kk++) {
            s[kk] *= SCALE;
            tmax = fmaxf(tmax, s[kk]);
        }
        float corr = __expf(mi - tmax);
        mi = tmax;
        li *= corr;
#pragma unroll
        for (int d = 0; d < 64; d++) acc[d] *= corr;

#pragma unroll 1
        for (int kk = 0; kk < 32; kk++) {
            float p = __expf(s[kk] - mi);
            li += p;
#pragma unroll
            for (int d4 = 0; d4 < 16; d4++) {
                float4 v4 = *(const float4*)&Vs[kk][d4 * 4];
                acc[d4 * 4 + 0] += p * v4.x;
                acc[d4 * 4 + 1] += p * v4.y;
                acc[d4 * 4 + 2] += p * v4.z;
                acc[d4 * 4 + 3] += p * v4.w;
            }
        }
    }

    const float inv = 1.f / li;
    size_t rowoff = (size_t)(rowbase + qt * 128 + tid) * DMODEL + h * HDIM;
#pragma unroll
    for (int d2 = 0; d2 < 32; d2++) {
        float v0 = acc[2 * d2] * inv, v1 = acc[2 * d2 + 1] * inv;
        __nv_bfloat16 h0 = __float2bfloat16(v0), h1 = __float2bfloat16(v1);
        __nv_bfloat16 l0 = __float2bfloat16(v0 - __bfloat162float(h0));
        __nv_bfloat16 l1 = __float2bfloat16(v1 - __bfloat162float(h1));
        __nv_bfloat162 hp; hp.x = h0; hp.y = h1;
        __nv_bfloat162 lp; lp.x = l0; lp.y = l1;
        *(__nv_bfloat162*)(g_ohi + rowoff + 2 * d2) = hp;
        *(__nv_bfloat162*)(g_olo + rowoff + 2 * d2) = lp;
    }
}

// ---------------------------------------------------------------------------
extern "C" void kernel_launch(void* const* d_in, const int* in_sizes, int n_in,
                              void* d_out, int out_size)
{
    const float* x    = (const float*)d_in[0];
    const float* wqkv = (const float*)d_in[1];
    const float* bqkv = (const float*)d_in[2];
    const float* wo   = (const float*)d_in[3];
    const float* bo   = (const float*)d_in[4];
    float* out = (float*)d_out;

    float* qkv_ptr;
    __nv_bfloat16 *xhi, *xlo, *wqh, *wql, *woh, *wol, *ohi, *olo;
    cudaGetSymbolAddress((void**)&qkv_ptr, g_qkv);
    cudaGetSymbolAddress((void**)&xhi, g_xhi);
    cudaGetSymbolAddress((void**)&xlo, g_xlo);
    cudaGetSymbolAddress((void**)&wqh, g_wqh);
    cudaGetSymbolAddress((void**)&wql, g_wql);
    cudaGetSymbolAddress((void**)&woh, g_woh);
    cudaGetSymbolAddress((void**)&wol, g_wol);
    cudaGetSymbolAddress((void**)&ohi, g_ohi);
    cudaGetSymbolAddress((void**)&olo, g_olo);

    cudaFuncSetAttribute(gemm_mma, cudaFuncAttributeMaxDynamicSharedMemorySize, SMEM_DYN);

    // 0) converts
    conv_x<<<MROWS, 256>>>(x);
    dim3 wb(32, 8);
    wconv<<<dim3(DQKV / 32, DMODEL / 32), wb>>>(wqkv, wqh, wql, DMODEL, DQKV);
    wconv<<<dim3(DMODEL / 32, DMODEL / 32), wb>>>(wo, woh, wol, DMODEL, DMODEL);

    // 1) QKV projection (HMMA)
    gemm_mma<<<dim3(DQKV / 128, MROWS / 128), 256, SMEM_DYN>>>(
        xhi, xlo, wqh, wql, bqkv, qkv_ptr, DQKV);

    // 2) attention (fp32), emits bf16 hi/lo
    attn_kernel<<<1024, 128>>>(qkv_ptr);

    // 3) output projection (HMMA)
    gemm_mma<<<dim3(DMODEL / 128, MROWS / 128), 256, SMEM_DYN>>>(
        ohi, olo, woh, wol, bo, out, DMODEL);
}

// round 4
// speedup vs baseline: 3.1180x; 2.1247x over previous
#include <cuda_runtime.h>
#include <cuda_bf16.h>
#include <cstdint>
#include <math.h>

#define BATCH   2
#define SEQ     8192
#define DMODEL  1024
#define NHEADS  16
#define HDIM    64
#define SEGLEN  2048
#define LSEG    1024
#define MROWS   8192
#define DQKV    3072

// ---------------- device scratch ----------------
__device__ __nv_bfloat16  g_qkvh[(size_t)MROWS * DQKV];
__device__ __nv_bfloat16  g_qkvl[(size_t)MROWS * DQKV];
__device__ __nv_bfloat16  g_xhi[(size_t)MROWS * DMODEL];
__device__ __nv_bfloat16  g_xlo[(size_t)MROWS * DMODEL];
__device__ __nv_bfloat16  g_wqh[(size_t)DQKV * DMODEL];
__device__ __nv_bfloat16  g_wql[(size_t)DQKV * DMODEL];
__device__ __nv_bfloat16  g_woh[(size_t)DMODEL * DMODEL];
__device__ __nv_bfloat16  g_wol[(size_t)DMODEL * DMODEL];
__device__ __nv_bfloat16  g_ohi[(size_t)MROWS * DMODEL];
__device__ __nv_bfloat16  g_olo[(size_t)MROWS * DMODEL];

// ---------------- PTX helpers ----------------
__device__ __forceinline__ uint32_t smem_u32(const void* p) {
    uint32_t a;
    asm("{ .reg .u64 t; cvta.to.shared.u64 t, %1; cvt.u32.u64 %0, t; }" : "=r"(a) : "l"(p));
    return a;
}
__device__ __forceinline__ void cp16(uint32_t s, const void* g) {
    asm volatile("cp.async.cg.shared.global [%0], [%1], 16;" :: "r"(s), "l"(g));
}
__device__ __forceinline__ void cp_commit() { asm volatile("cp.async.commit_group;"); }
__device__ __forceinline__ void cp_wait1()  { asm volatile("cp.async.wait_group 1;"); }
__device__ __forceinline__ void cp_wait0()  { asm volatile("cp.async.wait_group 0;"); }
__device__ __forceinline__ void ldm4(uint32_t* r, uint32_t addr) {
    asm volatile("ldmatrix.sync.aligned.m8n8.x4.shared.b16 {%0,%1,%2,%3}, [%4];"
        : "=r"(r[0]), "=r"(r[1]), "=r"(r[2]), "=r"(r[3]) : "r"(addr));
}
__device__ __forceinline__ void ldm4t(uint32_t* r, uint32_t addr) {
    asm volatile("ldmatrix.sync.aligned.m8n8.x4.trans.shared.b16 {%0,%1,%2,%3}, [%4];"
        : "=r"(r[0]), "=r"(r[1]), "=r"(r[2]), "=r"(r[3]) : "r"(addr));
}
__device__ __forceinline__ void mma16816(float* c, const uint32_t* a, const uint32_t* b) {
    asm volatile(
        "mma.sync.aligned.m16n8k16.row.col.f32.bf16.bf16.f32 "
        "{%0,%1,%2,%3}, {%4,%5,%6,%7}, {%8,%9}, {%0,%1,%2,%3};"
        : "+f"(c[0]), "+f"(c[1]), "+f"(c[2]), "+f"(c[3])
        : "r"(a[0]), "r"(a[1]), "r"(a[2]), "r"(a[3]), "r"(b[0]), "r"(b[1]));
}
__device__ __forceinline__ void pack_hl(float p0, float p1, uint32_t& h, uint32_t& l) {
    __nv_bfloat16 h0 = __float2bfloat16(p0), h1 = __float2bfloat16(p1);
    float r0 = p0 - __bfloat162float(h0), r1 = p1 - __bfloat162float(h1);
    __nv_bfloat162 hp; hp.x = h0; hp.y = h1;
    __nv_bfloat162 lp; lp.x = __float2bfloat16(r0); lp.y = __float2bfloat16(r1);
    h = *(uint32_t*)&hp;
    l = *(uint32_t*)&lp;
}

// ---------------------------------------------------------------------------
// converts
// ---------------------------------------------------------------------------
__global__ void __launch_bounds__(256) conv_x(const float* __restrict__ x) {
    int m = blockIdx.x;
    int b = m >> 12, rem = m & 4095, n = rem >> 10, l = rem & 1023;
    const float* src = x + ((size_t)(b * SEQ + n * SEGLEN + 2 * l)) * DMODEL;
    size_t dst = (size_t)m * DMODEL + threadIdx.x * 4;
    float4 v = *(const float4*)(src + threadIdx.x * 4);
    float vv[4] = {v.x, v.y, v.z, v.w};
    __nv_bfloat16 h[4], lo[4];
#pragma unroll
    for (int i = 0; i < 4; i++) {
        h[i] = __float2bfloat16(vv[i]);
        lo[i] = __float2bfloat16(vv[i] - __bfloat162float(h[i]));
    }
    *(uint2*)(g_xhi + dst) = *(uint2*)h;
    *(uint2*)(g_xlo + dst) = *(uint2*)lo;
}

__global__ void __launch_bounds__(256)
wconv(const float* __restrict__ W, __nv_bfloat16* __restrict__ Bh,
      __nv_bfloat16* __restrict__ Bl, int K, int N) {
    __shared__ float t[32][33];
    int n0 = blockIdx.x * 32, k0 = blockIdx.y * 32;
    int tx = threadIdx.x, ty = threadIdx.y;
    for (int i = ty; i < 32; i += 8)
        t[i][tx] = W[(size_t)(k0 + i) * N + n0 + tx];
    __syncthreads();
    for (int i = ty; i < 32; i += 8) {
        float v = t[tx][i];
        __nv_bfloat16 h = __float2bfloat16(v);
        __nv_bfloat16 lo = __float2bfloat16(v - __bfloat162float(h));
        size_t o = (size_t)(n0 + i) * K + k0 + tx;
        Bh[o] = h;
        Bl[o] = lo;
    }
}

// ---------------------------------------------------------------------------
// HMMA GEMM (as R3). OUT=0: fp32 C.  OUT=1: bf16 hi/lo pair outputs.
// ---------------------------------------------------------------------------
#define TS       10240
#define SMEM_G   (8 * TS)

template<int OUT>
__global__ void __launch_bounds__(256)
gemm_mma(const __nv_bfloat16* __restrict__ Ah, const __nv_bfloat16* __restrict__ Al,
         const __nv_bfloat16* __restrict__ Bh, const __nv_bfloat16* __restrict__ Bl,
         const float* __restrict__ bias, float* __restrict__ C,
         __nv_bfloat16* __restrict__ Ch, __nv_bfloat16* __restrict__ Cl, int Ncols)
{
    extern __shared__ char dsm[];
    __shared__ float biass[128];

    const int tid  = threadIdx.x;
    const int wid  = tid >> 5, lane = tid & 31;
    const int wm   = wid & 3, wn = wid >> 2;
    const int bn   = blockIdx.x * 128, bm = blockIdx.y * 128;
    const uint32_t sb = smem_u32(dsm);

    if (tid < 128) biass[tid] = bias[bn + tid];

    const __nv_bfloat16* srcs[4] = {
        Ah + (size_t)bm * DMODEL, Al + (size_t)bm * DMODEL,
        Bh + (size_t)bn * DMODEL, Bl + (size_t)bn * DMODEL };

    int crow[8], ckc[8], ctile[8];
#pragma unroll
    for (int i = 0; i < 8; i++) {
        int c = tid + i * 256;
        ctile[i] = c >> 9;
        crow[i]  = (c >> 2) & 127;
        ckc[i]   = (c & 3) * 8;
    }

    uint32_t aRow[2], bRow[4];
#pragma unroll
    for (int mt = 0; mt < 2; mt++)
        aRow[mt] = (uint32_t)((wm * 32 + mt * 16 + (lane & 15)) * 80 + (lane >> 4) * 16);
#pragma unroll
    for (int nt2 = 0; nt2 < 4; nt2++)
        bRow[nt2] = (uint32_t)((wn * 64 + nt2 * 16 + (lane & 7) + ((lane >> 4) << 3)) * 80
                               + ((lane >> 3) & 1) * 16);

    float acc[2][8][4];
#pragma unroll
    for (int mt = 0; mt < 2; mt++)
#pragma unroll
        for (int nt = 0; nt < 8; nt++)
#pragma unroll
            for (int j = 0; j < 4; j++) acc[mt][nt][j] = 0.f;

    {
#pragma unroll
        for (int i = 0; i < 8; i++)
            cp16(sb + ctile[i] * TS + (crow[i] * 40 + ckc[i]) * 2,
                 srcs[ctile[i]] + (size_t)crow[i] * DMODEL + ckc[i]);
        cp_commit();
    }

    const int NK = DMODEL / 32;
#pragma unroll 1
    for (int kc = 0; kc < NK; kc++) {
        int cur = kc & 1;
        if (kc + 1 < NK) {
            uint32_t sbase = sb + (cur ^ 1) * 4 * TS;
            int k0 = (kc + 1) * 32;
#pragma unroll
            for (int i = 0; i < 8; i++)
                cp16(sbase + ctile[i] * TS + (crow[i] * 40 + ckc[i]) * 2,
                     srcs[ctile[i]] + (size_t)crow[i] * DMODEL + k0 + ckc[i]);
            cp_commit();
            cp_wait1();
        } else {
            cp_wait0();
        }
        __syncthreads();

        uint32_t tb = sb + cur * 4 * TS;
#pragma unroll
        for (int ks = 0; ks < 2; ks++) {
            uint32_t ko = ks * 32;
            uint32_t ah[2][4], al[2][4], bh[4][4], bl[4][4];
#pragma unroll
            for (int mt = 0; mt < 2; mt++) {
                ldm4(ah[mt], tb + aRow[mt] + ko);
                ldm4(al[mt], tb + TS + aRow[mt] + ko);
            }
#pragma unroll
            for (int nt2 = 0; nt2 < 4; nt2++) {
                ldm4(bh[nt2], tb + 2 * TS + bRow[nt2] + ko);
                ldm4(bl[nt2], tb + 3 * TS + bRow[nt2] + ko);
            }
#pragma unroll
            for (int mt = 0; mt < 2; mt++)
#pragma unroll
                for (int nt = 0; nt < 8; nt++) {
                    int nt2 = nt >> 1, off = (nt & 1) * 2;
                    mma16816(acc[mt][nt], ah[mt], &bh[nt2][off]);
                    mma16816(acc[mt][nt], ah[mt], &bl[nt2][off]);
                    mma16816(acc[mt][nt], al[mt], &bh[nt2][off]);
                }
        }
        __syncthreads();
    }

    const int gq = lane >> 2, t4 = lane & 3;
#pragma unroll
    for (int mt = 0; mt < 2; mt++) {
        int row0 = bm + wm * 32 + mt * 16 + gq;
#pragma unroll
        for (int nt = 0; nt < 8; nt++) {
            int colL = wn * 64 + nt * 8 + t4 * 2;
            int col  = bn + colL;
            float v00 = acc[mt][nt][0] + biass[colL];
            float v01 = acc[mt][nt][1] + biass[colL + 1];
            float v10 = acc[mt][nt][2] + biass[colL];
            float v11 = acc[mt][nt][3] + biass[colL + 1];
            if (OUT == 0) {
                *(float2*)(C + (size_t)row0 * Ncols + col) = make_float2(v00, v01);
                *(float2*)(C + (size_t)(row0 + 8) * Ncols + col) = make_float2(v10, v11);
            } else {
                uint32_t h, l;
                pack_hl(v00, v01, h, l);
                *(uint32_t*)(Ch + (size_t)row0 * Ncols + col) = h;
                *(uint32_t*)(Cl + (size_t)row0 * Ncols + col) = l;
                pack_hl(v10, v11, h, l);
                *(uint32_t*)(Ch + (size_t)(row0 + 8) * Ncols + col) = h;
                *(uint32_t*)(Cl + (size_t)(row0 + 8) * Ncols + col) = l;
            }
        }
    }
}

// ---------------------------------------------------------------------------
// Flash attention on HMMA, bf16 hi/lo for QK and PV.
// Block = (bn, h, 128-q tile). 256 threads, warp = 16 q rows.
// K/V tiles: 64 keys, cp.async double-buffered, 144B row stride.
// ---------------------------------------------------------------------------
#define AST    144                    // smem row stride bytes (72 bf16)
#define KTB    (64 * AST)             // one 64-row tile = 9216B
#define STG    (4 * KTB)              // 4 tiles per stage = 36864B
#define SMEM_A (2 * STG)              // 73728B

__global__ void __launch_bounds__(256, 2)
attn_mma(const __nv_bfloat16* __restrict__ Qh, const __nv_bfloat16* __restrict__ Ql)
{
    extern __shared__ char dsm[];
    const uint32_t sb = smem_u32(dsm);

    const int tid  = threadIdx.x;
    const int wid  = tid >> 5, lane = tid & 31;
    const int gq = lane >> 2, t4 = lane & 3;
    const int qt = blockIdx.x & 7;
    const int h  = (blockIdx.x >> 3) & 15;
    const int bn = blockIdx.x >> 7;
    const size_t rowbase = (size_t)bn * LSEG;
    const size_t qrow0 = rowbase + qt * 128;

    // ---- stage Q (hi/lo) into smem, ldmatrix into registers ----
    {
#pragma unroll
        for (int i = 0; i < 8; i++) {
            int idx = tid + i * 256;           // 0..2047
            int t   = idx >> 10;               // 0 hi, 1 lo
            int r   = (idx >> 3) & 127;
            int c   = idx & 7;
            const __nv_bfloat16* src = (t == 0 ? Qh : Ql)
                + (qrow0 + r) * DQKV + h * HDIM + c * 8;
            cp16(sb + t * (128 * AST) + r * AST + c * 16, src);
        }
        cp_commit();
        cp_wait0();
        __syncthreads();
    }
    uint32_t qah[4][4], qal[4][4];
    {
        uint32_t qbase = sb + (wid * 16 + (lane & 15)) * AST + (lane >> 4) * 16;
#pragma unroll
        for (int ks = 0; ks < 4; ks++) {
            ldm4(qah[ks], qbase + ks * 32);
            ldm4(qal[ks], qbase + 128 * AST + ks * 32);
        }
    }
    __syncthreads();

    // ---- per-thread cp.async mapping for K/V stages ----
    int crow[8], cch[8], ctl[8];
#pragma unroll
    for (int i = 0; i < 8; i++) {
        int idx = tid + i * 256;               // 0..2047
        ctl[i]  = idx >> 9;                    // 0 Khi,1 Klo,2 Vhi,3 Vlo
        crow[i] = (idx >> 3) & 63;
        cch[i]  = idx & 7;
    }
    const __nv_bfloat16* kvsrc[4] = {
        Qh + rowbase * DQKV + DMODEL     + h * HDIM,
        Ql + rowbase * DQKV + DMODEL     + h * HDIM,
        Qh + rowbase * DQKV + 2 * DMODEL + h * HDIM,
        Ql + rowbase * DQKV + 2 * DMODEL + h * HDIM };

    // ldmatrix address bases
    const uint32_t kfrag = ((lane & 7) + ((lane >> 4) << 3)) * AST + ((lane >> 3) & 1) * 16;
    const uint32_t vfrag = ((lane & 7) + ((lane >> 3) & 1) * 8) * AST + (lane >> 4) * 16;

    float acc[8][4];
#pragma unroll
    for (int o = 0; o < 8; o++)
#pragma unroll
        for (int j = 0; j < 4; j++) acc[o][j] = 0.f;
    float m0 = -1e30f, m1 = -1e30f, l0 = 0.f, l1 = 0.f;

    // prefetch stage 0
    {
#pragma unroll
        for (int i = 0; i < 8; i++)
            cp16(sb + ctl[i] * KTB + crow[i] * AST + cch[i] * 16,
                 kvsrc[ctl[i]] + (size_t)crow[i] * DQKV + cch[i] * 8);
        cp_commit();
    }

    const int NT = LSEG / 64;     // 16 key tiles
#pragma unroll 1
    for (int kt = 0; kt < NT; kt++) {
        int cur = kt & 1;
        if (kt + 1 < NT) {
            uint32_t sbase = sb + (cur ^ 1) * STG;
            size_t roff = (size_t)(kt + 1) * 64;
#pragma unroll
            for (int i = 0; i < 8; i++)
                cp16(sbase + ctl[i] * KTB + crow[i] * AST + cch[i] * 16,
                     kvsrc[ctl[i]] + (roff + crow[i]) * DQKV + cch[i] * 8);
            cp_commit();
            cp_wait1();
        } else {
            cp_wait0();
        }
        __syncthreads();

        const uint32_t tb = sb + cur * STG;

        // ---- S = Q K^T (3 products) ----
        float sacc[8][4];
#pragma unroll
        for (int o = 0; o < 8; o++)
#pragma unroll
            for (int j = 0; j < 4; j++) sacc[o][j] = 0.f;

#pragma unroll
        for (int ks = 0; ks < 4; ks++) {
#pragma unroll
            for (int nt2 = 0; nt2 < 4; nt2++) {
                uint32_t kb = tb + nt2 * (16 * AST) + kfrag + ks * 32;
                uint32_t kh[4], kl[4];
                ldm4(kh, kb);
                ldm4(kl, kb + KTB);
#pragma unroll
                for (int half = 0; half < 2; half++) {
                    int nt = nt2 * 2 + half, off = half * 2;
                    mma16816(sacc[nt], qah[ks], &kh[off]);
                    mma16816(sacc[nt], qah[ks], &kl[off]);
                    mma16816(sacc[nt], qal[ks], &kh[off]);
                }
            }
        }

        // ---- online softmax on fragments ----
        const float SC = 0.125f;
        float mx0 = -1e30f, mx1 = -1e30f;
#pragma unroll
        for (int o = 0; o < 8; o++) {
            sacc[o][0] *= SC; sacc[o][1] *= SC; sacc[o][2] *= SC; sacc[o][3] *= SC;
            mx0 = fmaxf(mx0, fmaxf(sacc[o][0], sacc[o][1]));
            mx1 = fmaxf(mx1, fmaxf(sacc[o][2], sacc[o][3]));
        }
        mx0 = fmaxf(mx0, __shfl_xor_sync(0xffffffffu, mx0, 1));
        mx0 = fmaxf(mx0, __shfl_xor_sync(0xffffffffu, mx0, 2));
        mx1 = fmaxf(mx1, __shfl_xor_sync(0xffffffffu, mx1, 1));
        mx1 = fmaxf(mx1, __shfl_xor_sync(0xffffffffu, mx1, 2));
        float mn0 = fmaxf(m0, mx0), mn1 = fmaxf(m1, mx1);
        float c0 = __expf(m0 - mn0), c1 = __expf(m1 - mn1);
        m0 = mn0; m1 = mn1;
        float rs0 = 0.f, rs1 = 0.f;
#pragma unroll
        for (int o = 0; o < 8; o++) {
            sacc[o][0] = __expf(sacc[o][0] - mn0);
            sacc[o][1] = __expf(sacc[o][1] - mn0);
            sacc[o][2] = __expf(sacc[o][2] - mn1);
            sacc[o][3] = __expf(sacc[o][3] - mn1);
            rs0 += sacc[o][0] + sacc[o][1];
            rs1 += sacc[o][2] + sacc[o][3];
        }
        rs0 += __shfl_xor_sync(0xffffffffu, rs0, 1);
        rs0 += __shfl_xor_sync(0xffffffffu, rs0, 2);
        rs1 += __shfl_xor_sync(0xffffffffu, rs1, 1);
        rs1 += __shfl_xor_sync(0xffffffffu, rs1, 2);
        l0 = l0 * c0 + rs0;
        l1 = l1 * c1 + rs1;
#pragma unroll
        for (int o = 0; o < 8; o++) {
            acc[o][0] *= c0; acc[o][1] *= c0; acc[o][2] *= c1; acc[o][3] *= c1;
        }

        // ---- PV (3 products), P repacked from fragments ----
#pragma unroll
        for (int ks = 0; ks < 4; ks++) {
            uint32_t pah[4], pal[4];
            pack_hl(sacc[2 * ks][0],     sacc[2 * ks][1],     pah[0], pal[0]);
            pack_hl(sacc[2 * ks][2],     sacc[2 * ks][3],     pah[1], pal[1]);
            pack_hl(sacc[2 * ks + 1][0], sacc[2 * ks + 1][1], pah[2], pal[2]);
            pack_hl(sacc[2 * ks + 1][2], sacc[2 * ks + 1][3], pah[3], pal[3]);
#pragma unroll
            for (int db = 0; db < 4; db++) {
                uint32_t vb = tb + 2 * KTB + ks * (16 * AST) + vfrag + db * 32;
                uint32_t vh[4], vl[4];
                ldm4t(vh, vb);
                ldm4t(vl, vb + KTB);
#pragma unroll
                for (int half = 0; half < 2; half++) {
                    int o = db * 2 + half, off = half * 2;
                    mma16816(acc[o], pah, &vh[off]);
                    mma16816(acc[o], pah, &vl[off]);
                    mma16816(acc[o], pal, &vh[off]);
                }
            }
        }
        __syncthreads();
    }

    // ---- epilogue: normalize + write bf16 hi/lo ----
    float inv0 = 1.f / l0, inv1 = 1.f / l1;
    size_t r0 = qrow0 + wid * 16 + gq;
    size_t base0 = r0 * DMODEL + h * HDIM + t4 * 2;
    size_t base1 = (r0 + 8) * DMODEL + h * HDIM + t4 * 2;
#pragma unroll
    for (int o = 0; o < 8; o++) {
        uint32_t hh, ll;
        pack_hl(acc[o][0] * inv0, acc[o][1] * inv0, hh, ll);
        *(uint32_t*)(g_ohi + base0 + o * 8) = hh;
        *(uint32_t*)(g_olo + base0 + o * 8) = ll;
        pack_hl(acc[o][2] * inv1, acc[o][3] * inv1, hh, ll);
        *(uint32_t*)(g_ohi + base1 + o * 8) = hh;
        *(uint32_t*)(g_olo + base1 + o * 8) = ll;
    }
}

// ---------------------------------------------------------------------------
extern "C" void kernel_launch(void* const* d_in, const int* in_sizes, int n_in,
                              void* d_out, int out_size)
{
    const float* x    = (const float*)d_in[0];
    const float* wqkv = (const float*)d_in[1];
    const float* bqkv = (const float*)d_in[2];
    const float* wo   = (const float*)d_in[3];
    const float* bo   = (const float*)d_in[4];
    float* out = (float*)d_out;

    __nv_bfloat16 *qkvh, *qkvl, *xhi, *xlo, *wqh, *wql, *woh, *wol, *ohi, *olo;
    cudaGetSymbolAddress((void**)&qkvh, g_qkvh);
    cudaGetSymbolAddress((void**)&qkvl, g_qkvl);
    cudaGetSymbolAddress((void**)&xhi, g_xhi);
    cudaGetSymbolAddress((void**)&xlo, g_xlo);
    cudaGetSymbolAddress((void**)&wqh, g_wqh);
    cudaGetSymbolAddress((void**)&wql, g_wql);
    cudaGetSymbolAddress((void**)&woh, g_woh);
    cudaGetSymbolAddress((void**)&wol, g_wol);
    cudaGetSymbolAddress((void**)&ohi, g_ohi);
    cudaGetSymbolAddress((void**)&olo, g_olo);

    cudaFuncSetAttribute(gemm_mma<0>, cudaFuncAttributeMaxDynamicSharedMemorySize, SMEM_G);
    cudaFuncSetAttribute(gemm_mma<1>, cudaFuncAttributeMaxDynamicSharedMemorySize, SMEM_G);
    cudaFuncSetAttribute(attn_mma,    cudaFuncAttributeMaxDynamicSharedMemorySize, SMEM_A);

    conv_x<<<MROWS, 256>>>(x);
    dim3 wb(32, 8);
    wconv<<<dim3(DQKV / 32, DMODEL / 32), wb>>>(wqkv, wqh, wql, DMODEL, DQKV);
    wconv<<<dim3(DMODEL / 32, DMODEL / 32), wb>>>(wo, woh, wol, DMODEL, DMODEL);

    // 1) QKV projection -> bf16 hi/lo qkv
    gemm_mma<1><<<dim3(DQKV / 128, MROWS / 128), 256, SMEM_G>>>(
        xhi, xlo, wqh, wql, bqkv, nullptr, qkvh, qkvl, DQKV);

    // 2) attention (HMMA) -> bf16 hi/lo
    attn_mma<<<1024, 256, SMEM_A>>>(qkvh, qkvl);

    // 3) output projection -> fp32 out
    gemm_mma<0><<<dim3(DMODEL / 128, MROWS / 128), 256, SMEM_G>>>(
        ohi, olo, woh, wol, bo, out, nullptr, nullptr, DMODEL);
}

// round 5
// speedup vs baseline: 3.6563x; 1.1727x over previous
#include <cuda_runtime.h>
#include <cuda_bf16.h>
#include <cuda_fp16.h>
#include <cstdint>
#include <math.h>

#define BATCH   2
#define SEQ     8192
#define DMODEL  1024
#define NHEADS  16
#define HDIM    64
#define SEGLEN  2048
#define LSEG    1024
#define MROWS   8192
#define DQKV    3072

// ---------------- device scratch ----------------
__device__ __nv_bfloat16  g_qkvh[(size_t)MROWS * DQKV];   // attention inputs (bf16 hi/lo)
__device__ __nv_bfloat16  g_qkvl[(size_t)MROWS * DQKV];
__device__ __half         g_xhi[(size_t)MROWS * DMODEL];  // GEMM1 A (fp16 hi/lo)
__device__ __half         g_xlo[(size_t)MROWS * DMODEL];
__device__ __half         g_wq[(size_t)DQKV * DMODEL];    // weights^T single fp16
__device__ __half         g_wo[(size_t)DMODEL * DMODEL];
__device__ __half         g_ohi[(size_t)MROWS * DMODEL];  // attention out (fp16 hi/lo)
__device__ __half         g_olo[(size_t)MROWS * DMODEL];

// ---------------- PTX helpers ----------------
__device__ __forceinline__ uint32_t smem_u32(const void* p) {
    uint32_t a;
    asm("{ .reg .u64 t; cvta.to.shared.u64 t, %1; cvt.u32.u64 %0, t; }" : "=r"(a) : "l"(p));
    return a;
}
__device__ __forceinline__ void cp16(uint32_t s, const void* g) {
    asm volatile("cp.async.cg.shared.global [%0], [%1], 16;" :: "r"(s), "l"(g));
}
__device__ __forceinline__ void cp_commit() { asm volatile("cp.async.commit_group;"); }
__device__ __forceinline__ void cp_wait1()  { asm volatile("cp.async.wait_group 1;"); }
__device__ __forceinline__ void cp_wait0()  { asm volatile("cp.async.wait_group 0;"); }
__device__ __forceinline__ void ldm4(uint32_t* r, uint32_t addr) {
    asm volatile("ldmatrix.sync.aligned.m8n8.x4.shared.b16 {%0,%1,%2,%3}, [%4];"
        : "=r"(r[0]), "=r"(r[1]), "=r"(r[2]), "=r"(r[3]) : "r"(addr));
}
__device__ __forceinline__ void ldm4t(uint32_t* r, uint32_t addr) {
    asm volatile("ldmatrix.sync.aligned.m8n8.x4.trans.shared.b16 {%0,%1,%2,%3}, [%4];"
        : "=r"(r[0]), "=r"(r[1]), "=r"(r[2]), "=r"(r[3]) : "r"(addr));
}
__device__ __forceinline__ void mma_bf16(float* c, const uint32_t* a, const uint32_t* b) {
    asm volatile(
        "mma.sync.aligned.m16n8k16.row.col.f32.bf16.bf16.f32 "
        "{%0,%1,%2,%3}, {%4,%5,%6,%7}, {%8,%9}, {%0,%1,%2,%3};"
        : "+f"(c[0]), "+f"(c[1]), "+f"(c[2]), "+f"(c[3])
        : "r"(a[0]), "r"(a[1]), "r"(a[2]), "r"(a[3]), "r"(b[0]), "r"(b[1]));
}
__device__ __forceinline__ void mma_fp16(float* c, const uint32_t* a, const uint32_t* b) {
    asm volatile(
        "mma.sync.aligned.m16n8k16.row.col.f32.f16.f16.f32 "
        "{%0,%1,%2,%3}, {%4,%5,%6,%7}, {%8,%9}, {%0,%1,%2,%3};"
        : "+f"(c[0]), "+f"(c[1]), "+f"(c[2]), "+f"(c[3])
        : "r"(a[0]), "r"(a[1]), "r"(a[2]), "r"(a[3]), "r"(b[0]), "r"(b[1]));
}
// bf16 hi/lo pack
__device__ __forceinline__ void pack_hl(float p0, float p1, uint32_t& h, uint32_t& l) {
    __nv_bfloat16 h0 = __float2bfloat16(p0), h1 = __float2bfloat16(p1);
    float r0 = p0 - __bfloat162float(h0), r1 = p1 - __bfloat162float(h1);
    __nv_bfloat162 hp; hp.x = h0; hp.y = h1;
    __nv_bfloat162 lp; lp.x = __float2bfloat16(r0); lp.y = __float2bfloat16(r1);
    h = *(uint32_t*)&hp;
    l = *(uint32_t*)&lp;
}
// fp16 hi/lo pack
__device__ __forceinline__ void pack_hl16(float p0, float p1, uint32_t& h, uint32_t& l) {
    __half h0 = __float2half_rn(p0), h1 = __float2half_rn(p1);
    float r0 = p0 - __half2float(h0), r1 = p1 - __half2float(h1);
    __half2 hp = __halves2half2(h0, h1);
    __half2 lp = __halves2half2(__float2half_rn(r0), __float2half_rn(r1));
    h = *(uint32_t*)&hp;
    l = *(uint32_t*)&lp;
}

// ---------------------------------------------------------------------------
// convert+gather x -> fp16 hi/lo
// ---------------------------------------------------------------------------
__global__ void __launch_bounds__(256) conv_x(const float* __restrict__ x) {
    int m = blockIdx.x;
    int b = m >> 12, rem = m & 4095, n = rem >> 10, l = rem & 1023;
    const float* src = x + ((size_t)(b * SEQ + n * SEGLEN + 2 * l)) * DMODEL;
    size_t dst = (size_t)m * DMODEL + threadIdx.x * 4;
    float4 v = *(const float4*)(src + threadIdx.x * 4);
    uint32_t h0, l0, h1, l1;
    pack_hl16(v.x, v.y, h0, l0);
    pack_hl16(v.z, v.w, h1, l1);
    uint2 hh = make_uint2(h0, h1), ll = make_uint2(l0, l1);
    *(uint2*)(g_xhi + dst) = hh;
    *(uint2*)(g_xlo + dst) = ll;
}

// ---------------------------------------------------------------------------
// weight transpose + convert: W[K x N] fp32 -> B[N x K] single fp16
// ---------------------------------------------------------------------------
__global__ void __launch_bounds__(256)
wconv(const float* __restrict__ W, __half* __restrict__ Bt, int K, int N) {
    __shared__ float t[32][33];
    int n0 = blockIdx.x * 32, k0 = blockIdx.y * 32;
    int tx = threadIdx.x, ty = threadIdx.y;
    for (int i = ty; i < 32; i += 8)
        t[i][tx] = W[(size_t)(k0 + i) * N + n0 + tx];
    __syncthreads();
    for (int i = ty; i < 32; i += 8)
        Bt[(size_t)(n0 + i) * K + k0 + tx] = __float2half_rn(t[tx][i]);
}

// ---------------------------------------------------------------------------
// fp16 2-product HMMA GEMM: C = (Ah+Al)[M x 1024] * B[N x 1024]^T + bias
// 128x128 tile, BK=32, 256 thr, 3-tile stage (Ah, Al, B), double-buffered.
// OUT=0: fp32 C.  OUT=1: bf16 hi/lo pair (qkv for attention).
// ---------------------------------------------------------------------------
#define TS       10240                // 128 rows * 40 elem * 2B
#define STAGE_G  (3 * TS)             // 30720
#define SMEM_G   (2 * STAGE_G)        // 61440

template<int OUT>
__global__ void __launch_bounds__(256)
gemm_mma(const __half* __restrict__ Ah, const __half* __restrict__ Al,
         const __half* __restrict__ B,
         const float* __restrict__ bias, float* __restrict__ C,
         __nv_bfloat16* __restrict__ Ch, __nv_bfloat16* __restrict__ Cl, int Ncols)
{
    extern __shared__ char dsm[];
    __shared__ float biass[128];

    const int tid  = threadIdx.x;
    const int wid  = tid >> 5, lane = tid & 31;
    const int wm   = wid & 3, wn = wid >> 2;
    const int bn   = blockIdx.x * 128, bm = blockIdx.y * 128;
    const uint32_t sb = smem_u32(dsm);

    if (tid < 128) biass[tid] = bias[bn + tid];

    const __half* srcs[3] = {
        Ah + (size_t)bm * DMODEL, Al + (size_t)bm * DMODEL,
        B  + (size_t)bn * DMODEL };

    // cp.async mapping: 6 x 16B per thread (3 tiles x 128 rows x 4 chunks)
    int crow[6], ckc[6], ctile[6];
#pragma unroll
    for (int i = 0; i < 6; i++) {
        int c = tid + i * 256;        // 0..1535
        ctile[i] = c >> 9;
        crow[i]  = (c >> 2) & 127;
        ckc[i]   = (c & 3) * 8;
    }

    uint32_t aRow[2], bRow[4];
#pragma unroll
    for (int mt = 0; mt < 2; mt++)
        aRow[mt] = (uint32_t)((wm * 32 + mt * 16 + (lane & 15)) * 80 + (lane >> 4) * 16);
#pragma unroll
    for (int nt2 = 0; nt2 < 4; nt2++)
        bRow[nt2] = (uint32_t)((wn * 64 + nt2 * 16 + (lane & 7) + ((lane >> 4) << 3)) * 80
                               + ((lane >> 3) & 1) * 16);

    float acc[2][8][4];
#pragma unroll
    for (int mt = 0; mt < 2; mt++)
#pragma unroll
        for (int nt = 0; nt < 8; nt++)
#pragma unroll
            for (int j = 0; j < 4; j++) acc[mt][nt][j] = 0.f;

    {
#pragma unroll
        for (int i = 0; i < 6; i++)
            cp16(sb + ctile[i] * TS + (crow[i] * 40 + ckc[i]) * 2,
                 srcs[ctile[i]] + (size_t)crow[i] * DMODEL + ckc[i]);
        cp_commit();
    }

    const int NK = DMODEL / 32;
#pragma unroll 1
    for (int kc = 0; kc < NK; kc++) {
        int cur = kc & 1;
        if (kc + 1 < NK) {
            uint32_t sbase = sb + (cur ^ 1) * STAGE_G;
            int k0 = (kc + 1) * 32;
#pragma unroll
            for (int i = 0; i < 6; i++)
                cp16(sbase + ctile[i] * TS + (crow[i] * 40 + ckc[i]) * 2,
                     srcs[ctile[i]] + (size_t)crow[i] * DMODEL + k0 + ckc[i]);
            cp_commit();
            cp_wait1();
        } else {
            cp_wait0();
        }
        __syncthreads();

        uint32_t tb = sb + cur * STAGE_G;
#pragma unroll
        for (int ks = 0; ks < 2; ks++) {
            uint32_t ko = ks * 32;
            uint32_t ah[2][4], al[2][4], bb[4][4];
#pragma unroll
            for (int mt = 0; mt < 2; mt++) {
                ldm4(ah[mt], tb + aRow[mt] + ko);
                ldm4(al[mt], tb + TS + aRow[mt] + ko);
            }
#pragma unroll
            for (int nt2 = 0; nt2 < 4; nt2++)
                ldm4(bb[nt2], tb + 2 * TS + bRow[nt2] + ko);
#pragma unroll
            for (int mt = 0; mt < 2; mt++)
#pragma unroll
                for (int nt = 0; nt < 8; nt++) {
                    int nt2 = nt >> 1, off = (nt & 1) * 2;
                    mma_fp16(acc[mt][nt], ah[mt], &bb[nt2][off]);
                    mma_fp16(acc[mt][nt], al[mt], &bb[nt2][off]);
                }
        }
        __syncthreads();
    }

    const int gq = lane >> 2, t4 = lane & 3;
#pragma unroll
    for (int mt = 0; mt < 2; mt++) {
        int row0 = bm + wm * 32 + mt * 16 + gq;
#pragma unroll
        for (int nt = 0; nt < 8; nt++) {
            int colL = wn * 64 + nt * 8 + t4 * 2;
            int col  = bn + colL;
            float v00 = acc[mt][nt][0] + biass[colL];
            float v01 = acc[mt][nt][1] + biass[colL + 1];
            float v10 = acc[mt][nt][2] + biass[colL];
            float v11 = acc[mt][nt][3] + biass[colL + 1];
            if (OUT == 0) {
                *(float2*)(C + (size_t)row0 * Ncols + col) = make_float2(v00, v01);
                *(float2*)(C + (size_t)(row0 + 8) * Ncols + col) = make_float2(v10, v11);
            } else {
                uint32_t h, l;
                pack_hl(v00, v01, h, l);
                *(uint32_t*)(Ch + (size_t)row0 * Ncols + col) = h;
                *(uint32_t*)(Cl + (size_t)row0 * Ncols + col) = l;
                pack_hl(v10, v11, h, l);
                *(uint32_t*)(Ch + (size_t)(row0 + 8) * Ncols + col) = h;
                *(uint32_t*)(Cl + (size_t)(row0 + 8) * Ncols + col) = l;
            }
        }
    }
}

// ---------------------------------------------------------------------------
// Flash attention on HMMA, bf16 hi/lo 3-product (unchanged math from R4).
// Epilogue emits fp16 hi/lo for GEMM2.
// ---------------------------------------------------------------------------
#define AST    144
#define KTB    (64 * AST)
#define STG    (4 * KTB)
#define SMEM_A (2 * STG)

__global__ void __launch_bounds__(256, 2)
attn_mma(const __nv_bfloat16* __restrict__ Qh, const __nv_bfloat16* __restrict__ Ql)
{
    extern __shared__ char dsm[];
    const uint32_t sb = smem_u32(dsm);

    const int tid  = threadIdx.x;
    const int wid  = tid >> 5, lane = tid & 31;
    const int gq = lane >> 2, t4 = lane & 3;
    const int qt = blockIdx.x & 7;
    const int h  = (blockIdx.x >> 3) & 15;
    const int bn = blockIdx.x >> 7;
    const size_t rowbase = (size_t)bn * LSEG;
    const size_t qrow0 = rowbase + qt * 128;

    {
#pragma unroll
        for (int i = 0; i < 8; i++) {
            int idx = tid + i * 256;
            int t   = idx >> 10;
            int r   = (idx >> 3) & 127;
            int c   = idx & 7;
            const __nv_bfloat16* src = (t == 0 ? Qh : Ql)
                + (qrow0 + r) * DQKV + h * HDIM + c * 8;
            cp16(sb + t * (128 * AST) + r * AST + c * 16, src);
        }
        cp_commit();
        cp_wait0();
        __syncthreads();
    }
    uint32_t qah[4][4], qal[4][4];
    {
        uint32_t qbase = sb + (wid * 16 + (lane & 15)) * AST + (lane >> 4) * 16;
#pragma unroll
        for (int ks = 0; ks < 4; ks++) {
            ldm4(qah[ks], qbase + ks * 32);
            ldm4(qal[ks], qbase + 128 * AST + ks * 32);
        }
    }
    __syncthreads();

    int crow[8], cch[8], ctl[8];
#pragma unroll
    for (int i = 0; i < 8; i++) {
        int idx = tid + i * 256;
        ctl[i]  = idx >> 9;
        crow[i] = (idx >> 3) & 63;
        cch[i]  = idx & 7;
    }
    const __nv_bfloat16* kvsrc[4] = {
        Qh + rowbase * DQKV + DMODEL     + h * HDIM,
        Ql + rowbase * DQKV + DMODEL     + h * HDIM,
        Qh + rowbase * DQKV + 2 * DMODEL + h * HDIM,
        Ql + rowbase * DQKV + 2 * DMODEL + h * HDIM };

    const uint32_t kfrag = ((lane & 7) + ((lane >> 4) << 3)) * AST + ((lane >> 3) & 1) * 16;
    const uint32_t vfrag = ((lane & 7) + ((lane >> 3) & 1) * 8) * AST + (lane >> 4) * 16;

    float acc[8][4];
#pragma unroll
    for (int o = 0; o < 8; o++)
#pragma unroll
        for (int j = 0; j < 4; j++) acc[o][j] = 0.f;
    float m0 = -1e30f, m1 = -1e30f, l0 = 0.f, l1 = 0.f;

    {
#pragma unroll
        for (int i = 0; i < 8; i++)
            cp16(sb + ctl[i] * KTB + crow[i] * AST + cch[i] * 16,
                 kvsrc[ctl[i]] + (size_t)crow[i] * DQKV + cch[i] * 8);
        cp_commit();
    }

    const int NT = LSEG / 64;
#pragma unroll 1
    for (int kt = 0; kt < NT; kt++) {
        int cur = kt & 1;
        if (kt + 1 < NT) {
            uint32_t sbase = sb + (cur ^ 1) * STG;
            size_t roff = (size_t)(kt + 1) * 64;
#pragma unroll
            for (int i = 0; i < 8; i++)
                cp16(sbase + ctl[i] * KTB + crow[i] * AST + cch[i] * 16,
                     kvsrc[ctl[i]] + (roff + crow[i]) * DQKV + cch[i] * 8);
            cp_commit();
            cp_wait1();
        } else {
            cp_wait0();
        }
        __syncthreads();

        const uint32_t tb = sb + cur * STG;

        float sacc[8][4];
#pragma unroll
        for (int o = 0; o < 8; o++)
#pragma unroll
            for (int j = 0; j < 4; j++) sacc[o][j] = 0.f;

#pragma unroll
        for (int ks = 0; ks < 4; ks++) {
#pragma unroll
            for (int nt2 = 0; nt2 < 4; nt2++) {
                uint32_t kb = tb + nt2 * (16 * AST) + kfrag + ks * 32;
                uint32_t kh[4], kl[4];
                ldm4(kh, kb);
                ldm4(kl, kb + KTB);
#pragma unroll
                for (int half = 0; half < 2; half++) {
                    int nt = nt2 * 2 + half, off = half * 2;
                    mma_bf16(sacc[nt], qah[ks], &kh[off]);
                    mma_bf16(sacc[nt], qah[ks], &kl[off]);
                    mma_bf16(sacc[nt], qal[ks], &kh[off]);
                }
            }
        }

        const float SC = 0.125f;
        float mx0 = -1e30f, mx1 = -1e30f;
#pragma unroll
        for (int o = 0; o < 8; o++) {
            sacc[o][0] *= SC; sacc[o][1] *= SC; sacc[o][2] *= SC; sacc[o][3] *= SC;
            mx0 = fmaxf(mx0, fmaxf(sacc[o][0], sacc[o][1]));
            mx1 = fmaxf(mx1, fmaxf(sacc[o][2], sacc[o][3]));
        }
        mx0 = fmaxf(mx0, __shfl_xor_sync(0xffffffffu, mx0, 1));
        mx0 = fmaxf(mx0, __shfl_xor_sync(0xffffffffu, mx0, 2));
        mx1 = fmaxf(mx1, __shfl_xor_sync(0xffffffffu, mx1, 1));
        mx1 = fmaxf(mx1, __shfl_xor_sync(0xffffffffu, mx1, 2));
        float mn0 = fmaxf(m0, mx0), mn1 = fmaxf(m1, mx1);
        float c0 = __expf(m0 - mn0), c1 = __expf(m1 - mn1);
        m0 = mn0; m1 = mn1;
        float rs0 = 0.f, rs1 = 0.f;
#pragma unroll
        for (int o = 0; o < 8; o++) {
            sacc[o][0] = __expf(sacc[o][0] - mn0);
            sacc[o][1] = __expf(sacc[o][1] - mn0);
            sacc[o][2] = __expf(sacc[o][2] - mn1);
            sacc[o][3] = __expf(sacc[o][3] - mn1);
            rs0 += sacc[o][0] + sacc[o][1];
            rs1 += sacc[o][2] + sacc[o][3];
        }
        rs0 += __shfl_xor_sync(0xffffffffu, rs0, 1);
        rs0 += __shfl_xor_sync(0xffffffffu, rs0, 2);
        rs1 += __shfl_xor_sync(0xffffffffu, rs1, 1);
        rs1 += __shfl_xor_sync(0xffffffffu, rs1, 2);
        l0 = l0 * c0 + rs0;
        l1 = l1 * c1 + rs1;
#pragma unroll
        for (int o = 0; o < 8; o++) {
            acc[o][0] *= c0; acc[o][1] *= c0; acc[o][2] *= c1; acc[o][3] *= c1;
        }

#pragma unroll
        for (int ks = 0; ks < 4; ks++) {
            uint32_t pah[4], pal[4];
            pack_hl(sacc[2 * ks][0],     sacc[2 * ks][1],     pah[0], pal[0]);
            pack_hl(sacc[2 * ks][2],     sacc[2 * ks][3],     pah[1], pal[1]);
            pack_hl(sacc[2 * ks + 1][0], sacc[2 * ks + 1][1], pah[2], pal[2]);
            pack_hl(sacc[2 * ks + 1][2], sacc[2 * ks + 1][3], pah[3], pal[3]);
#pragma unroll
            for (int db = 0; db < 4; db++) {
                uint32_t vb = tb + 2 * KTB + ks * (16 * AST) + vfrag + db * 32;
                uint32_t vh[4], vl[4];
                ldm4t(vh, vb);
                ldm4t(vl, vb + KTB);
#pragma unroll
                for (int half = 0; half < 2; half++) {
                    int o = db * 2 + half, off = half * 2;
                    mma_bf16(acc[o], pah, &vh[off]);
                    mma_bf16(acc[o], pah, &vl[off]);
                    mma_bf16(acc[o], pal, &vh[off]);
                }
            }
        }
        __syncthreads();
    }

    // epilogue: normalize + write fp16 hi/lo
    float inv0 = 1.f / l0, inv1 = 1.f / l1;
    size_t r0 = qrow0 + wid * 16 + gq;
    size_t base0 = r0 * DMODEL + h * HDIM + t4 * 2;
    size_t base1 = (r0 + 8) * DMODEL + h * HDIM + t4 * 2;
#pragma unroll
    for (int o = 0; o < 8; o++) {
        uint32_t hh, ll;
        pack_hl16(acc[o][0] * inv0, acc[o][1] * inv0, hh, ll);
        *(uint32_t*)(g_ohi + base0 + o * 8) = hh;
        *(uint32_t*)(g_olo + base0 + o * 8) = ll;
        pack_hl16(acc[o][2] * inv1, acc[o][3] * inv1, hh, ll);
        *(uint32_t*)(g_ohi + base1 + o * 8) = hh;
        *(uint32_t*)(g_olo + base1 + o * 8) = ll;
    }
}

// ---------------------------------------------------------------------------
extern "C" void kernel_launch(void* const* d_in, const int* in_sizes, int n_in,
                              void* d_out, int out_size)
{
    const float* x    = (const float*)d_in[0];
    const float* wqkv = (const float*)d_in[1];
    const float* bqkv = (const float*)d_in[2];
    const float* wo   = (const float*)d_in[3];
    const float* bo   = (const float*)d_in[4];
    float* out = (float*)d_out;

    __nv_bfloat16 *qkvh, *qkvl;
    __half *xhi, *xlo, *wq, *wo16, *ohi, *olo;
    cudaGetSymbolAddress((void**)&qkvh, g_qkvh);
    cudaGetSymbolAddress((void**)&qkvl, g_qkvl);
    cudaGetSymbolAddress((void**)&xhi, g_xhi);
    cudaGetSymbolAddress((void**)&xlo, g_xlo);
    cudaGetSymbolAddress((void**)&wq, g_wq);
    cudaGetSymbolAddress((void**)&wo16, g_wo);
    cudaGetSymbolAddress((void**)&ohi, g_ohi);
    cudaGetSymbolAddress((void**)&olo, g_olo);

    cudaFuncSetAttribute(gemm_mma<0>, cudaFuncAttributeMaxDynamicSharedMemorySize, SMEM_G);
    cudaFuncSetAttribute(gemm_mma<1>, cudaFuncAttributeMaxDynamicSharedMemorySize, SMEM_G);
    cudaFuncSetAttribute(attn_mma,    cudaFuncAttributeMaxDynamicSharedMemorySize, SMEM_A);

    conv_x<<<MROWS, 256>>>(x);
    dim3 wb(32, 8);
    wconv<<<dim3(DQKV / 32, DMODEL / 32), wb>>>(wqkv, wq, DMODEL, DQKV);
    wconv<<<dim3(DMODEL / 32, DMODEL / 32), wb>>>(wo, wo16, DMODEL, DMODEL);

    // 1) QKV projection (fp16 2-product) -> bf16 hi/lo qkv
    gemm_mma<1><<<dim3(DQKV / 128, MROWS / 128), 256, SMEM_G>>>(
        xhi, xlo, wq, bqkv, nullptr, qkvh, qkvl, DQKV);

    // 2) attention (bf16 3-product) -> fp16 hi/lo
    attn_mma<<<1024, 256, SMEM_A>>>(qkvh, qkvl);

    // 3) output projection (fp16 2-product) -> fp32 out
    gemm_mma<0><<<dim3(DMODEL / 128, MROWS / 128), 256, SMEM_G>>>(
        ohi, olo, wo16, bo, out, nullptr, nullptr, DMODEL);
}

// round 6
// speedup vs baseline: 4.2543x; 1.1636x over previous
#include <cuda_runtime.h>
#include <cuda_bf16.h>
#include <cuda_fp16.h>
#include <cstdint>
#include <math.h>

#define BATCH   2
#define SEQ     8192
#define DMODEL  1024
#define NHEADS  16
#define HDIM    64
#define SEGLEN  2048
#define LSEG    1024
#define MROWS   8192
#define DQKV    3072

// ---------------- device scratch ----------------
__device__ __half  g_qkvh[(size_t)MROWS * DQKV];   // qkv hi (fp16)
__device__ __half  g_qkvl[(size_t)MROWS * DQKV];   // qkv lo (fp16) -- only Q part read
__device__ __half  g_xhi[(size_t)MROWS * DMODEL];
__device__ __half  g_xlo[(size_t)MROWS * DMODEL];
__device__ __half  g_wq[(size_t)DQKV * DMODEL];
__device__ __half  g_wo[(size_t)DMODEL * DMODEL];
__device__ __half  g_ohi[(size_t)MROWS * DMODEL];
__device__ __half  g_olo[(size_t)MROWS * DMODEL];

// ---------------- PTX helpers ----------------
__device__ __forceinline__ uint32_t smem_u32(const void* p) {
    uint32_t a;
    asm("{ .reg .u64 t; cvta.to.shared.u64 t, %1; cvt.u32.u64 %0, t; }" : "=r"(a) : "l"(p));
    return a;
}
__device__ __forceinline__ void cp16(uint32_t s, const void* g) {
    asm volatile("cp.async.cg.shared.global [%0], [%1], 16;" :: "r"(s), "l"(g));
}
__device__ __forceinline__ void cp_commit() { asm volatile("cp.async.commit_group;"); }
__device__ __forceinline__ void cp_wait1()  { asm volatile("cp.async.wait_group 1;"); }
__device__ __forceinline__ void cp_wait0()  { asm volatile("cp.async.wait_group 0;"); }
__device__ __forceinline__ void ldm4(uint32_t* r, uint32_t addr) {
    asm volatile("ldmatrix.sync.aligned.m8n8.x4.shared.b16 {%0,%1,%2,%3}, [%4];"
        : "=r"(r[0]), "=r"(r[1]), "=r"(r[2]), "=r"(r[3]) : "r"(addr));
}
__device__ __forceinline__ void ldm4t(uint32_t* r, uint32_t addr) {
    asm volatile("ldmatrix.sync.aligned.m8n8.x4.trans.shared.b16 {%0,%1,%2,%3}, [%4];"
        : "=r"(r[0]), "=r"(r[1]), "=r"(r[2]), "=r"(r[3]) : "r"(addr));
}
__device__ __forceinline__ void mma_fp16(float* c, const uint32_t* a, const uint32_t* b) {
    asm volatile(
        "mma.sync.aligned.m16n8k16.row.col.f32.f16.f16.f32 "
        "{%0,%1,%2,%3}, {%4,%5,%6,%7}, {%8,%9}, {%0,%1,%2,%3};"
        : "+f"(c[0]), "+f"(c[1]), "+f"(c[2]), "+f"(c[3])
        : "r"(a[0]), "r"(a[1]), "r"(a[2]), "r"(a[3]), "r"(b[0]), "r"(b[1]));
}
__device__ __forceinline__ void pack_hl16(float p0, float p1, uint32_t& h, uint32_t& l) {
    __half h0 = __float2half_rn(p0), h1 = __float2half_rn(p1);
    float r0 = p0 - __half2float(h0), r1 = p1 - __half2float(h1);
    __half2 hp = __halves2half2(h0, h1);
    __half2 lp = __halves2half2(__float2half_rn(r0), __float2half_rn(r1));
    h = *(uint32_t*)&hp;
    l = *(uint32_t*)&lp;
}

// ---------------------------------------------------------------------------
// convert+gather x -> fp16 hi/lo
// ---------------------------------------------------------------------------
__global__ void __launch_bounds__(256) conv_x(const float* __restrict__ x) {
    int m = blockIdx.x;
    int b = m >> 12, rem = m & 4095, n = rem >> 10, l = rem & 1023;
    const float* src = x + ((size_t)(b * SEQ + n * SEGLEN + 2 * l)) * DMODEL;
    size_t dst = (size_t)m * DMODEL + threadIdx.x * 4;
    float4 v = *(const float4*)(src + threadIdx.x * 4);
    uint32_t h0, l0, h1, l1;
    pack_hl16(v.x, v.y, h0, l0);
    pack_hl16(v.z, v.w, h1, l1);
    *(uint2*)(g_xhi + dst) = make_uint2(h0, h1);
    *(uint2*)(g_xlo + dst) = make_uint2(l0, l1);
}

__global__ void __launch_bounds__(256)
wconv(const float* __restrict__ W, __half* __restrict__ Bt, int K, int N) {
    __shared__ float t[32][33];
    int n0 = blockIdx.x * 32, k0 = blockIdx.y * 32;
    int tx = threadIdx.x, ty = threadIdx.y;
    for (int i = ty; i < 32; i += 8)
        t[i][tx] = W[(size_t)(k0 + i) * N + n0 + tx];
    __syncthreads();
    for (int i = ty; i < 32; i += 8)
        Bt[(size_t)(n0 + i) * K + k0 + tx] = __float2half_rn(t[tx][i]);
}

// ---------------------------------------------------------------------------
// fp16 2-product GEMM, 3-stage cp.async pipeline, 1 sync per chunk.
// OUT=0: fp32 C.  OUT=1: fp16 hi/lo (qkv).
// ---------------------------------------------------------------------------
#define TS       10240                // 128 rows * 40 elem * 2B
#define STAGE_G  (3 * TS)
#define SMEM_G   (3 * STAGE_G)        // 92160

template<int OUT>
__global__ void __launch_bounds__(256)
gemm_mma(const __half* __restrict__ Ah, const __half* __restrict__ Al,
         const __half* __restrict__ B,
         const float* __restrict__ bias, float* __restrict__ C,
         __half* __restrict__ Ch, __half* __restrict__ Cl, int Ncols)
{
    extern __shared__ char dsm[];
    __shared__ float biass[128];

    const int tid  = threadIdx.x;
    const int wid  = tid >> 5, lane = tid & 31;
    const int wm   = wid & 3, wn = wid >> 2;
    const int bn   = blockIdx.x * 128, bm = blockIdx.y * 128;
    const uint32_t sb = smem_u32(dsm);

    if (tid < 128) biass[tid] = bias[bn + tid];

    const __half* srcs[3] = {
        Ah + (size_t)bm * DMODEL, Al + (size_t)bm * DMODEL,
        B  + (size_t)bn * DMODEL };

    int crow[6], ckc[6], ctile[6];
#pragma unroll
    for (int i = 0; i < 6; i++) {
        int c = tid + i * 256;
        ctile[i] = c >> 9;
        crow[i]  = (c >> 2) & 127;
        ckc[i]   = (c & 3) * 8;
    }

    uint32_t aRow[2], bRow[4];
#pragma unroll
    for (int mt = 0; mt < 2; mt++)
        aRow[mt] = (uint32_t)((wm * 32 + mt * 16 + (lane & 15)) * 80 + (lane >> 4) * 16);
#pragma unroll
    for (int nt2 = 0; nt2 < 4; nt2++)
        bRow[nt2] = (uint32_t)((wn * 64 + nt2 * 16 + (lane & 7) + ((lane >> 4) << 3)) * 80
                               + ((lane >> 3) & 1) * 16);

    float acc[2][8][4];
#pragma unroll
    for (int mt = 0; mt < 2; mt++)
#pragma unroll
        for (int nt = 0; nt < 8; nt++)
#pragma unroll
            for (int j = 0; j < 4; j++) acc[mt][nt][j] = 0.f;

    const int NK = DMODEL / 32;      // 32
    // prefetch stages 0,1
#pragma unroll
    for (int s = 0; s < 2; s++) {
        uint32_t sbase = sb + s * STAGE_G;
        int k0 = s * 32;
#pragma unroll
        for (int i = 0; i < 6; i++)
            cp16(sbase + ctile[i] * TS + (crow[i] * 40 + ckc[i]) * 2,
                 srcs[ctile[i]] + (size_t)crow[i] * DMODEL + k0 + ckc[i]);
        cp_commit();
    }

#pragma unroll 1
    for (int kc = 0; kc < NK; kc++) {
        if (kc < NK - 1) cp_wait1(); else cp_wait0();
        __syncthreads();
        if (kc + 2 < NK) {
            int sidx = (kc + 2) % 3;
            uint32_t sbase = sb + sidx * STAGE_G;
            int k0 = (kc + 2) * 32;
#pragma unroll
            for (int i = 0; i < 6; i++)
                cp16(sbase + ctile[i] * TS + (crow[i] * 40 + ckc[i]) * 2,
                     srcs[ctile[i]] + (size_t)crow[i] * DMODEL + k0 + ckc[i]);
            cp_commit();
        }

        uint32_t tb = sb + (kc % 3) * STAGE_G;
#pragma unroll
        for (int ks = 0; ks < 2; ks++) {
            uint32_t ko = ks * 32;
            uint32_t ah[2][4], al[2][4], bb[4][4];
#pragma unroll
            for (int mt = 0; mt < 2; mt++) {
                ldm4(ah[mt], tb + aRow[mt] + ko);
                ldm4(al[mt], tb + TS + aRow[mt] + ko);
            }
#pragma unroll
            for (int nt2 = 0; nt2 < 4; nt2++)
                ldm4(bb[nt2], tb + 2 * TS + bRow[nt2] + ko);
#pragma unroll
            for (int mt = 0; mt < 2; mt++)
#pragma unroll
                for (int nt = 0; nt < 8; nt++) {
                    int nt2 = nt >> 1, off = (nt & 1) * 2;
                    mma_fp16(acc[mt][nt], ah[mt], &bb[nt2][off]);
                    mma_fp16(acc[mt][nt], al[mt], &bb[nt2][off]);
                }
        }
    }

    const int gq = lane >> 2, t4 = lane & 3;
#pragma unroll
    for (int mt = 0; mt < 2; mt++) {
        int row0 = bm + wm * 32 + mt * 16 + gq;
#pragma unroll
        for (int nt = 0; nt < 8; nt++) {
            int colL = wn * 64 + nt * 8 + t4 * 2;
            int col  = bn + colL;
            float v00 = acc[mt][nt][0] + biass[colL];
            float v01 = acc[mt][nt][1] + biass[colL + 1];
            float v10 = acc[mt][nt][2] + biass[colL];
            float v11 = acc[mt][nt][3] + biass[colL + 1];
            if (OUT == 0) {
                *(float2*)(C + (size_t)row0 * Ncols + col) = make_float2(v00, v01);
                *(float2*)(C + (size_t)(row0 + 8) * Ncols + col) = make_float2(v10, v11);
            } else {
                uint32_t h, l;
                pack_hl16(v00, v01, h, l);
                *(uint32_t*)(Ch + (size_t)row0 * Ncols + col) = h;
                *(uint32_t*)(Cl + (size_t)row0 * Ncols + col) = l;
                pack_hl16(v10, v11, h, l);
                *(uint32_t*)(Ch + (size_t)(row0 + 8) * Ncols + col) = h;
                *(uint32_t*)(Cl + (size_t)(row0 + 8) * Ncols + col) = l;
            }
        }
    }
}

// ---------------------------------------------------------------------------
// Flash attention: Q,P fp16 hi/lo (2-product); K,V single fp16 (hi only).
// 3-stage KV pipeline (K,V tiles of 64 keys), 1 sync per tile.
// ---------------------------------------------------------------------------
#define AST     144
#define KTB     (64 * AST)            // 9216
#define STG_A   (2 * KTB)             // 18432 (K + V)
#define SMEM_A  (3 * STG_A)           // 55296 (also >= Q staging 36864)

__global__ void __launch_bounds__(256, 2)
attn_mma(const __half* __restrict__ Qh, const __half* __restrict__ Ql)
{
    extern __shared__ char dsm[];
    const uint32_t sb = smem_u32(dsm);

    const int tid  = threadIdx.x;
    const int wid  = tid >> 5, lane = tid & 31;
    const int gq = lane >> 2, t4 = lane & 3;
    const int qt = blockIdx.x & 7;
    const int h  = (blockIdx.x >> 3) & 15;
    const int bn = blockIdx.x >> 7;
    const size_t rowbase = (size_t)bn * LSEG;
    const size_t qrow0 = rowbase + qt * 128;

    // ---- stage Q (hi/lo fp16) into smem, ldsm to regs ----
    {
#pragma unroll
        for (int i = 0; i < 8; i++) {
            int idx = tid + i * 256;           // 0..2047
            int t   = idx >> 10;               // 0 hi, 1 lo
            int r   = (idx >> 3) & 127;
            int c   = idx & 7;
            const __half* src = (t == 0 ? Qh : Ql)
                + (qrow0 + r) * DQKV + h * HDIM + c * 8;
            cp16(sb + t * (128 * AST) + r * AST + c * 16, src);
        }
        cp_commit();
        cp_wait0();
        __syncthreads();
    }
    uint32_t qah[4][4], qal[4][4];
    {
        uint32_t qbase = sb + (wid * 16 + (lane & 15)) * AST + (lane >> 4) * 16;
#pragma unroll
        for (int ks = 0; ks < 4; ks++) {
            ldm4(qah[ks], qbase + ks * 32);
            ldm4(qal[ks], qbase + 128 * AST + ks * 32);
        }
    }
    __syncthreads();

    // ---- KV cp.async mapping: 2 tiles x 64 rows x 8 chunks = 1024 ----
    int crow[4], cch[4], ctl[4];
#pragma unroll
    for (int i = 0; i < 4; i++) {
        int idx = tid + i * 256;               // 0..1023
        ctl[i]  = idx >> 9;                    // 0 K, 1 V
        crow[i] = (idx >> 3) & 63;
        cch[i]  = idx & 7;
    }
    const __half* kvsrc[2] = {
        Qh + rowbase * DQKV + DMODEL     + h * HDIM,
        Qh + rowbase * DQKV + 2 * DMODEL + h * HDIM };

    const uint32_t kfrag = ((lane & 7) + ((lane >> 4) << 3)) * AST + ((lane >> 3) & 1) * 16;
    const uint32_t vfrag = ((lane & 7) + ((lane >> 3) & 1) * 8) * AST + (lane >> 4) * 16;

    float acc[8][4];
#pragma unroll
    for (int o = 0; o < 8; o++)
#pragma unroll
        for (int j = 0; j < 4; j++) acc[o][j] = 0.f;
    float m0 = -1e30f, m1 = -1e30f, l0 = 0.f, l1 = 0.f;

    const int NT = LSEG / 64;     // 16
    // prefetch stages 0,1
#pragma unroll
    for (int s = 0; s < 2; s++) {
        uint32_t sbase = sb + s * STG_A;
        size_t roff = (size_t)s * 64;
#pragma unroll
        for (int i = 0; i < 4; i++)
            cp16(sbase + ctl[i] * KTB + crow[i] * AST + cch[i] * 16,
                 kvsrc[ctl[i]] + (roff + crow[i]) * DQKV + cch[i] * 8);
        cp_commit();
    }

#pragma unroll 1
    for (int kt = 0; kt < NT; kt++) {
        if (kt < NT - 1) cp_wait1(); else cp_wait0();
        __syncthreads();
        if (kt + 2 < NT) {
            uint32_t sbase = sb + ((kt + 2) % 3) * STG_A;
            size_t roff = (size_t)(kt + 2) * 64;
#pragma unroll
            for (int i = 0; i < 4; i++)
                cp16(sbase + ctl[i] * KTB + crow[i] * AST + cch[i] * 16,
                     kvsrc[ctl[i]] + (roff + crow[i]) * DQKV + cch[i] * 8);
            cp_commit();
        }

        const uint32_t tb = sb + (kt % 3) * STG_A;

        // ---- S = Q K^T (2 products, K single fp16) ----
        float sacc[8][4];
#pragma unroll
        for (int o = 0; o < 8; o++)
#pragma unroll
            for (int j = 0; j < 4; j++) sacc[o][j] = 0.f;

#pragma unroll
        for (int ks = 0; ks < 4; ks++) {
#pragma unroll
            for (int nt2 = 0; nt2 < 4; nt2++) {
                uint32_t kh[4];
                ldm4(kh, tb + nt2 * (16 * AST) + kfrag + ks * 32);
#pragma unroll
                for (int half = 0; half < 2; half++) {
                    int nt = nt2 * 2 + half, off = half * 2;
                    mma_fp16(sacc[nt], qah[ks], &kh[off]);
                    mma_fp16(sacc[nt], qal[ks], &kh[off]);
                }
            }
        }

        // ---- online softmax ----
        const float SC = 0.125f;
        float mx0 = -1e30f, mx1 = -1e30f;
#pragma unroll
        for (int o = 0; o < 8; o++) {
            sacc[o][0] *= SC; sacc[o][1] *= SC; sacc[o][2] *= SC; sacc[o][3] *= SC;
            mx0 = fmaxf(mx0, fmaxf(sacc[o][0], sacc[o][1]));
            mx1 = fmaxf(mx1, fmaxf(sacc[o][2], sacc[o][3]));
        }
        mx0 = fmaxf(mx0, __shfl_xor_sync(0xffffffffu, mx0, 1));
        mx0 = fmaxf(mx0, __shfl_xor_sync(0xffffffffu, mx0, 2));
        mx1 = fmaxf(mx1, __shfl_xor_sync(0xffffffffu, mx1, 1));
        mx1 = fmaxf(mx1, __shfl_xor_sync(0xffffffffu, mx1, 2));
        float mn0 = fmaxf(m0, mx0), mn1 = fmaxf(m1, mx1);
        float c0 = __expf(m0 - mn0), c1 = __expf(m1 - mn1);
        m0 = mn0; m1 = mn1;
        float rs0 = 0.f, rs1 = 0.f;
#pragma unroll
        for (int o = 0; o < 8; o++) {
            sacc[o][0] = __expf(sacc[o][0] - mn0);
            sacc[o][1] = __expf(sacc[o][1] - mn0);
            sacc[o][2] = __expf(sacc[o][2] - mn1);
            sacc[o][3] = __expf(sacc[o][3] - mn1);
            rs0 += sacc[o][0] + sacc[o][1];
            rs1 += sacc[o][2] + sacc[o][3];
        }
        rs0 += __shfl_xor_sync(0xffffffffu, rs0, 1);
        rs0 += __shfl_xor_sync(0xffffffffu, rs0, 2);
        rs1 += __shfl_xor_sync(0xffffffffu, rs1, 1);
        rs1 += __shfl_xor_sync(0xffffffffu, rs1, 2);
        l0 = l0 * c0 + rs0;
        l1 = l1 * c1 + rs1;
#pragma unroll
        for (int o = 0; o < 8; o++) {
            acc[o][0] *= c0; acc[o][1] *= c0; acc[o][2] *= c1; acc[o][3] *= c1;
        }

        // ---- PV (2 products, V single fp16) ----
#pragma unroll
        for (int ks = 0; ks < 4; ks++) {
            uint32_t pah[4], pal[4];
            pack_hl16(sacc[2 * ks][0],     sacc[2 * ks][1],     pah[0], pal[0]);
            pack_hl16(sacc[2 * ks][2],     sacc[2 * ks][3],     pah[1], pal[1]);
            pack_hl16(sacc[2 * ks + 1][0], sacc[2 * ks + 1][1], pah[2], pal[2]);
            pack_hl16(sacc[2 * ks + 1][2], sacc[2 * ks + 1][3], pah[3], pal[3]);
#pragma unroll
            for (int db = 0; db < 4; db++) {
                uint32_t vh[4];
                ldm4t(vh, tb + KTB + ks * (16 * AST) + vfrag + db * 32);
#pragma unroll
                for (int half = 0; half < 2; half++) {
                    int o = db * 2 + half, off = half * 2;
                    mma_fp16(acc[o], pah, &vh[off]);
                    mma_fp16(acc[o], pal, &vh[off]);
                }
            }
        }
    }

    // ---- epilogue: normalize + write fp16 hi/lo ----
    float inv0 = 1.f / l0, inv1 = 1.f / l1;
    size_t r0 = qrow0 + wid * 16 + gq;
    size_t base0 = r0 * DMODEL + h * HDIM + t4 * 2;
    size_t base1 = (r0 + 8) * DMODEL + h * HDIM + t4 * 2;
#pragma unroll
    for (int o = 0; o < 8; o++) {
        uint32_t hh, ll;
        pack_hl16(acc[o][0] * inv0, acc[o][1] * inv0, hh, ll);
        *(uint32_t*)(g_ohi + base0 + o * 8) = hh;
        *(uint32_t*)(g_olo + base0 + o * 8) = ll;
        pack_hl16(acc[o][2] * inv1, acc[o][3] * inv1, hh, ll);
        *(uint32_t*)(g_ohi + base1 + o * 8) = hh;
        *(uint32_t*)(g_olo + base1 + o * 8) = ll;
    }
}

// ---------------------------------------------------------------------------
extern "C" void kernel_launch(void* const* d_in, const int* in_sizes, int n_in,
                              void* d_out, int out_size)
{
    const float* x    = (const float*)d_in[0];
    const float* wqkv = (const float*)d_in[1];
    const float* bqkv = (const float*)d_in[2];
    const float* wo   = (const float*)d_in[3];
    const float* bo   = (const float*)d_in[4];
    float* out = (float*)d_out;

    __half *qkvh, *qkvl, *xhi, *xlo, *wq, *wo16, *ohi, *olo;
    cudaGetSymbolAddress((void**)&qkvh, g_qkvh);
    cudaGetSymbolAddress((void**)&qkvl, g_qkvl);
    cudaGetSymbolAddress((void**)&xhi, g_xhi);
    cudaGetSymbolAddress((void**)&xlo, g_xlo);
    cudaGetSymbolAddress((void**)&wq, g_wq);
    cudaGetSymbolAddress((void**)&wo16, g_wo);
    cudaGetSymbolAddress((void**)&ohi, g_ohi);
    cudaGetSymbolAddress((void**)&olo, g_olo);

    cudaFuncSetAttribute(gemm_mma<0>, cudaFuncAttributeMaxDynamicSharedMemorySize, SMEM_G);
    cudaFuncSetAttribute(gemm_mma<1>, cudaFuncAttributeMaxDynamicSharedMemorySize, SMEM_G);
    cudaFuncSetAttribute(attn_mma,    cudaFuncAttributeMaxDynamicSharedMemorySize, SMEM_A);

    conv_x<<<MROWS, 256>>>(x);
    dim3 wb(32, 8);
    wconv<<<dim3(DQKV / 32, DMODEL / 32), wb>>>(wqkv, wq, DMODEL, DQKV);
    wconv<<<dim3(DMODEL / 32, DMODEL / 32), wb>>>(wo, wo16, DMODEL, DMODEL);

    gemm_mma<1><<<dim3(DQKV / 128, MROWS / 128), 256, SMEM_G>>>(
        xhi, xlo, wq, bqkv, nullptr, qkvh, qkvl, DQKV);

    attn_mma<<<1024, 256, SMEM_A>>>(qkvh, qkvl);

    gemm_mma<0><<<dim3(DMODEL / 128, MROWS / 128), 256, SMEM_G>>>(
        ohi, olo, wo16, bo, out, nullptr, nullptr, DMODEL);
}

// round 7
// speedup vs baseline: 5.9462x; 1.3977x over previous
#include <cuda_runtime.h>
#include <cuda_bf16.h>
#include <cuda_fp16.h>
#include <cstdint>
#include <math.h>

#define BATCH   2
#define SEQ     8192
#define DMODEL  1024
#define NHEADS  16
#define HDIM    64
#define SEGLEN  2048
#define LSEG    1024
#define MROWS   8192
#define DQKV    3072

// ---------------- device scratch ----------------
__device__ __half  g_qkvh[(size_t)MROWS * DQKV];   // qkv hi (fp16)
__device__ __half  g_qkvl[(size_t)MROWS * DQKV];   // qkv lo (only Q part read)
__device__ __half  g_xh [(size_t)MROWS * DMODEL];  // gathered x, single fp16
__device__ __half  g_wq [(size_t)DQKV * DMODEL];
__device__ __half  g_wo [(size_t)DMODEL * DMODEL];
__device__ __half  g_oh [(size_t)MROWS * DMODEL];  // attn out, single fp16

// ---------------- PTX helpers ----------------
__device__ __forceinline__ uint32_t smem_u32(const void* p) {
    uint32_t a;
    asm("{ .reg .u64 t; cvta.to.shared.u64 t, %1; cvt.u32.u64 %0, t; }" : "=r"(a) : "l"(p));
    return a;
}
__device__ __forceinline__ void cp16(uint32_t s, const void* g) {
    asm volatile("cp.async.cg.shared.global [%0], [%1], 16;" :: "r"(s), "l"(g));
}
__device__ __forceinline__ void cp_commit() { asm volatile("cp.async.commit_group;"); }
__device__ __forceinline__ void cp_wait2()  { asm volatile("cp.async.wait_group 2;"); }
__device__ __forceinline__ void cp_wait1()  { asm volatile("cp.async.wait_group 1;"); }
__device__ __forceinline__ void cp_wait0()  { asm volatile("cp.async.wait_group 0;"); }
__device__ __forceinline__ void ldm4(uint32_t* r, uint32_t addr) {
    asm volatile("ldmatrix.sync.aligned.m8n8.x4.shared.b16 {%0,%1,%2,%3}, [%4];"
        : "=r"(r[0]), "=r"(r[1]), "=r"(r[2]), "=r"(r[3]) : "r"(addr));
}
__device__ __forceinline__ void ldm4t(uint32_t* r, uint32_t addr) {
    asm volatile("ldmatrix.sync.aligned.m8n8.x4.trans.shared.b16 {%0,%1,%2,%3}, [%4];"
        : "=r"(r[0]), "=r"(r[1]), "=r"(r[2]), "=r"(r[3]) : "r"(addr));
}
__device__ __forceinline__ void mma_fp16(float* c, const uint32_t* a, const uint32_t* b) {
    asm volatile(
        "mma.sync.aligned.m16n8k16.row.col.f32.f16.f16.f32 "
        "{%0,%1,%2,%3}, {%4,%5,%6,%7}, {%8,%9}, {%0,%1,%2,%3};"
        : "+f"(c[0]), "+f"(c[1]), "+f"(c[2]), "+f"(c[3])
        : "r"(a[0]), "r"(a[1]), "r"(a[2]), "r"(a[3]), "r"(b[0]), "r"(b[1]));
}
__device__ __forceinline__ void pack_hl16(float p0, float p1, uint32_t& h, uint32_t& l) {
    __half h0 = __float2half_rn(p0), h1 = __float2half_rn(p1);
    float r0 = p0 - __half2float(h0), r1 = p1 - __half2float(h1);
    __half2 hp = __halves2half2(h0, h1);
    __half2 lp = __halves2half2(__float2half_rn(r0), __float2half_rn(r1));
    h = *(uint32_t*)&hp;
    l = *(uint32_t*)&lp;
}

// ---------------------------------------------------------------------------
// convert+gather x -> single fp16
// ---------------------------------------------------------------------------
__global__ void __launch_bounds__(256) conv_x(const float* __restrict__ x) {
    int m = blockIdx.x;
    int b = m >> 12, rem = m & 4095, n = rem >> 10, l = rem & 1023;
    const float* src = x + ((size_t)(b * SEQ + n * SEGLEN + 2 * l)) * DMODEL;
    size_t dst = (size_t)m * DMODEL + threadIdx.x * 4;
    float4 v = *(const float4*)(src + threadIdx.x * 4);
    __half2 a = __halves2half2(__float2half_rn(v.x), __float2half_rn(v.y));
    __half2 b2 = __halves2half2(__float2half_rn(v.z), __float2half_rn(v.w));
    uint2 o;
    o.x = *(uint32_t*)&a;
    o.y = *(uint32_t*)&b2;
    *(uint2*)(g_xh + dst) = o;
}

__global__ void __launch_bounds__(256)
wconv(const float* __restrict__ W, __half* __restrict__ Bt, int K, int N) {
    __shared__ float t[32][33];
    int n0 = blockIdx.x * 32, k0 = blockIdx.y * 32;
    int tx = threadIdx.x, ty = threadIdx.y;
    for (int i = ty; i < 32; i += 8)
        t[i][tx] = W[(size_t)(k0 + i) * N + n0 + tx];
    __syncthreads();
    for (int i = ty; i < 32; i += 8)
        Bt[(size_t)(n0 + i) * K + k0 + tx] = __float2half_rn(t[tx][i]);
}

// ---------------------------------------------------------------------------
// single-product fp16 GEMM: C = A[M x 1024] * B[N x 1024]^T + bias
// 128x128 tile, BK=32, 256 thr, 4-stage cp.async pipeline, 1 sync per chunk.
// OUT=0: fp32 C.  OUT=1: fp16 hi/lo pair (qkv).
// ---------------------------------------------------------------------------
#define TS       10240                // 128 rows * 40 elem * 2B
#define STAGE_G  (2 * TS)             // 20480 (A + B)
#define SMEM_G   (4 * STAGE_G)        // 81920

template<int OUT>
__global__ void __launch_bounds__(256)
gemm_mma(const __half* __restrict__ A, const __half* __restrict__ B,
         const float* __restrict__ bias, float* __restrict__ C,
         __half* __restrict__ Ch, __half* __restrict__ Cl, int Ncols)
{
    extern __shared__ char dsm[];
    __shared__ float biass[128];

    const int tid  = threadIdx.x;
    const int wid  = tid >> 5, lane = tid & 31;
    const int wm   = wid & 3, wn = wid >> 2;
    const int bn   = blockIdx.x * 128, bm = blockIdx.y * 128;
    const uint32_t sb = smem_u32(dsm);

    if (tid < 128) biass[tid] = bias[bn + tid];

    const __half* srcs[2] = { A + (size_t)bm * DMODEL, B + (size_t)bn * DMODEL };

    // cp.async mapping: 4 x 16B per thread (2 tiles x 128 rows x 4 chunks)
    int crow[4], ckc[4], ctile[4];
#pragma unroll
    for (int i = 0; i < 4; i++) {
        int c = tid + i * 256;         // 0..1023
        ctile[i] = c >> 9;
        crow[i]  = (c >> 2) & 127;
        ckc[i]   = (c & 3) * 8;
    }

    uint32_t aRow[2], bRow[4];
#pragma unroll
    for (int mt = 0; mt < 2; mt++)
        aRow[mt] = (uint32_t)((wm * 32 + mt * 16 + (lane & 15)) * 80 + (lane >> 4) * 16);
#pragma unroll
    for (int nt2 = 0; nt2 < 4; nt2++)
        bRow[nt2] = (uint32_t)((wn * 64 + nt2 * 16 + (lane & 7) + ((lane >> 4) << 3)) * 80
                               + ((lane >> 3) & 1) * 16);

    float acc[2][8][4];
#pragma unroll
    for (int mt = 0; mt < 2; mt++)
#pragma unroll
        for (int nt = 0; nt < 8; nt++)
#pragma unroll
            for (int j = 0; j < 4; j++) acc[mt][nt][j] = 0.f;

    const int NK = DMODEL / 32;       // 32
    // prefetch stages 0..2
#pragma unroll
    for (int s = 0; s < 3; s++) {
        uint32_t sbase = sb + s * STAGE_G;
        int k0 = s * 32;
#pragma unroll
        for (int i = 0; i < 4; i++)
            cp16(sbase + ctile[i] * TS + (crow[i] * 40 + ckc[i]) * 2,
                 srcs[ctile[i]] + (size_t)crow[i] * DMODEL + k0 + ckc[i]);
        cp_commit();
    }

#pragma unroll 1
    for (int kc = 0; kc < NK; kc++) {
        cp_wait2();
        __syncthreads();
        if (kc + 3 < NK) {
            uint32_t sbase = sb + ((kc + 3) & 3) * STAGE_G;
            int k0 = (kc + 3) * 32;
#pragma unroll
            for (int i = 0; i < 4; i++)
                cp16(sbase + ctile[i] * TS + (crow[i] * 40 + ckc[i]) * 2,
                     srcs[ctile[i]] + (size_t)crow[i] * DMODEL + k0 + ckc[i]);
        }
        cp_commit();

        uint32_t tb = sb + (kc & 3) * STAGE_G;
#pragma unroll
        for (int ks = 0; ks < 2; ks++) {
            uint32_t ko = ks * 32;
            uint32_t ah[2][4], bb[4][4];
#pragma unroll
            for (int mt = 0; mt < 2; mt++)
                ldm4(ah[mt], tb + aRow[mt] + ko);
#pragma unroll
            for (int nt2 = 0; nt2 < 4; nt2++)
                ldm4(bb[nt2], tb + TS + bRow[nt2] + ko);
#pragma unroll
            for (int mt = 0; mt < 2; mt++)
#pragma unroll
                for (int nt = 0; nt < 8; nt++)
                    mma_fp16(acc[mt][nt], ah[mt], &bb[nt >> 1][(nt & 1) * 2]);
        }
    }

    const int gq = lane >> 2, t4 = lane & 3;
#pragma unroll
    for (int mt = 0; mt < 2; mt++) {
        int row0 = bm + wm * 32 + mt * 16 + gq;
#pragma unroll
        for (int nt = 0; nt < 8; nt++) {
            int colL = wn * 64 + nt * 8 + t4 * 2;
            int col  = bn + colL;
            float v00 = acc[mt][nt][0] + biass[colL];
            float v01 = acc[mt][nt][1] + biass[colL + 1];
            float v10 = acc[mt][nt][2] + biass[colL];
            float v11 = acc[mt][nt][3] + biass[colL + 1];
            if (OUT == 0) {
                *(float2*)(C + (size_t)row0 * Ncols + col) = make_float2(v00, v01);
                *(float2*)(C + (size_t)(row0 + 8) * Ncols + col) = make_float2(v10, v11);
            } else {
                uint32_t h, l;
                pack_hl16(v00, v01, h, l);
                *(uint32_t*)(Ch + (size_t)row0 * Ncols + col) = h;
                *(uint32_t*)(Cl + (size_t)row0 * Ncols + col) = l;
                pack_hl16(v10, v11, h, l);
                *(uint32_t*)(Ch + (size_t)(row0 + 8) * Ncols + col) = h;
                *(uint32_t*)(Cl + (size_t)(row0 + 8) * Ncols + col) = l;
            }
        }
    }
}

// ---------------------------------------------------------------------------
// Flash attention: Q,P fp16 hi/lo (2-product); K,V single fp16.
// 3-stage KV pipeline, 1 sync per tile. Epilogue writes single fp16.
// ---------------------------------------------------------------------------
#define AST     144
#define KTB     (64 * AST)            // 9216
#define STG_A   (2 * KTB)             // 18432 (K + V)
#define SMEM_A  (3 * STG_A)           // 55296 (>= Q staging 36864)

__global__ void __launch_bounds__(256, 2)
attn_mma(const __half* __restrict__ Qh, const __half* __restrict__ Ql)
{
    extern __shared__ char dsm[];
    const uint32_t sb = smem_u32(dsm);

    const int tid  = threadIdx.x;
    const int wid  = tid >> 5, lane = tid & 31;
    const int gq = lane >> 2, t4 = lane & 3;
    const int qt = blockIdx.x & 7;
    const int h  = (blockIdx.x >> 3) & 15;
    const int bn = blockIdx.x >> 7;
    const size_t rowbase = (size_t)bn * LSEG;
    const size_t qrow0 = rowbase + qt * 128;

    // ---- stage Q (hi/lo) into smem, ldsm to regs ----
    {
#pragma unroll
        for (int i = 0; i < 8; i++) {
            int idx = tid + i * 256;
            int t   = idx >> 10;
            int r   = (idx >> 3) & 127;
            int c   = idx & 7;
            const __half* src = (t == 0 ? Qh : Ql)
                + (qrow0 + r) * DQKV + h * HDIM + c * 8;
            cp16(sb + t * (128 * AST) + r * AST + c * 16, src);
        }
        cp_commit();
        cp_wait0();
        __syncthreads();
    }
    uint32_t qah[4][4], qal[4][4];
    {
        uint32_t qbase = sb + (wid * 16 + (lane & 15)) * AST + (lane >> 4) * 16;
#pragma unroll
        for (int ks = 0; ks < 4; ks++) {
            ldm4(qah[ks], qbase + ks * 32);
            ldm4(qal[ks], qbase + 128 * AST + ks * 32);
        }
    }
    __syncthreads();

    int crow[4], cch[4], ctl[4];
#pragma unroll
    for (int i = 0; i < 4; i++) {
        int idx = tid + i * 256;
        ctl[i]  = idx >> 9;
        crow[i] = (idx >> 3) & 63;
        cch[i]  = idx & 7;
    }
    const __half* kvsrc[2] = {
        Qh + rowbase * DQKV + DMODEL     + h * HDIM,
        Qh + rowbase * DQKV + 2 * DMODEL + h * HDIM };

    const uint32_t kfrag = ((lane & 7) + ((lane >> 4) << 3)) * AST + ((lane >> 3) & 1) * 16;
    const uint32_t vfrag = ((lane & 7) + ((lane >> 3) & 1) * 8) * AST + (lane >> 4) * 16;

    float acc[8][4];
#pragma unroll
    for (int o = 0; o < 8; o++)
#pragma unroll
        for (int j = 0; j < 4; j++) acc[o][j] = 0.f;
    float m0 = -1e30f, m1 = -1e30f, l0 = 0.f, l1 = 0.f;

    const int NT = LSEG / 64;
#pragma unroll
    for (int s = 0; s < 2; s++) {
        uint32_t sbase = sb + s * STG_A;
        size_t roff = (size_t)s * 64;
#pragma unroll
        for (int i = 0; i < 4; i++)
            cp16(sbase + ctl[i] * KTB + crow[i] * AST + cch[i] * 16,
                 kvsrc[ctl[i]] + (roff + crow[i]) * DQKV + cch[i] * 8);
        cp_commit();
    }

#pragma unroll 1
    for (int kt = 0; kt < NT; kt++) {
        if (kt < NT - 1) cp_wait1(); else cp_wait0();
        __syncthreads();
        if (kt + 2 < NT) {
            uint32_t sbase = sb + ((kt + 2) % 3) * STG_A;
            size_t roff = (size_t)(kt + 2) * 64;
#pragma unroll
            for (int i = 0; i < 4; i++)
                cp16(sbase + ctl[i] * KTB + crow[i] * AST + cch[i] * 16,
                     kvsrc[ctl[i]] + (roff + crow[i]) * DQKV + cch[i] * 8);
            cp_commit();
        }

        const uint32_t tb = sb + (kt % 3) * STG_A;

        float sacc[8][4];
#pragma unroll
        for (int o = 0; o < 8; o++)
#pragma unroll
            for (int j = 0; j < 4; j++) sacc[o][j] = 0.f;

#pragma unroll
        for (int ks = 0; ks < 4; ks++) {
#pragma unroll
            for (int nt2 = 0; nt2 < 4; nt2++) {
                uint32_t kh[4];
                ldm4(kh, tb + nt2 * (16 * AST) + kfrag + ks * 32);
#pragma unroll
                for (int half = 0; half < 2; half++) {
                    int nt = nt2 * 2 + half, off = half * 2;
                    mma_fp16(sacc[nt], qah[ks], &kh[off]);
                    mma_fp16(sacc[nt], qal[ks], &kh[off]);
                }
            }
        }

        const float SC = 0.125f;
        float mx0 = -1e30f, mx1 = -1e30f;
#pragma unroll
        for (int o = 0; o < 8; o++) {
            sacc[o][0] *= SC; sacc[o][1] *= SC; sacc[o][2] *= SC; sacc[o][3] *= SC;
            mx0 = fmaxf(mx0, fmaxf(sacc[o][0], sacc[o][1]));
            mx1 = fmaxf(mx1, fmaxf(sacc[o][2], sacc[o][3]));
        }
        mx0 = fmaxf(mx0, __shfl_xor_sync(0xffffffffu, mx0, 1));
        mx0 = fmaxf(mx0, __shfl_xor_sync(0xffffffffu, mx0, 2));
        mx1 = fmaxf(mx1, __shfl_xor_sync(0xffffffffu, mx1, 1));
        mx1 = fmaxf(mx1, __shfl_xor_sync(0xffffffffu, mx1, 2));
        float mn0 = fmaxf(m0, mx0), mn1 = fmaxf(m1, mx1);
        float c0 = __expf(m0 - mn0), c1 = __expf(m1 - mn1);
        m0 = mn0; m1 = mn1;
        float rs0 = 0.f, rs1 = 0.f;
#pragma unroll
        for (int o = 0; o < 8; o++) {
            sacc[o][0] = __expf(sacc[o][0] - mn0);
            sacc[o][1] = __expf(sacc[o][1] - mn0);
            sacc[o][2] = __expf(sacc[o][2] - mn1);
            sacc[o][3] = __expf(sacc[o][3] - mn1);
            rs0 += sacc[o][0] + sacc[o][1];
            rs1 += sacc[o][2] + sacc[o][3];
        }
        rs0 += __shfl_xor_sync(0xffffffffu, rs0, 1);
        rs0 += __shfl_xor_sync(0xffffffffu, rs0, 2);
        rs1 += __shfl_xor_sync(0xffffffffu, rs1, 1);
        rs1 += __shfl_xor_sync(0xffffffffu, rs1, 2);
        l0 = l0 * c0 + rs0;
        l1 = l1 * c1 + rs1;
#pragma unroll
        for (int o = 0; o < 8; o++) {
            acc[o][0] *= c0; acc[o][1] *= c0; acc[o][2] *= c1; acc[o][3] *= c1;
        }

#pragma unroll
        for (int ks = 0; ks < 4; ks++) {
            uint32_t pah[4], pal[4];
            pack_hl16(sacc[2 * ks][0],     sacc[2 * ks][1],     pah[0], pal[0]);
            pack_hl16(sacc[2 * ks][2],     sacc[2 * ks][3],     pah[1], pal[1]);
            pack_hl16(sacc[2 * ks + 1][0], sacc[2 * ks + 1][1], pah[2], pal[2]);
            pack_hl16(sacc[2 * ks + 1][2], sacc[2 * ks + 1][3], pah[3], pal[3]);
#pragma unroll
            for (int db = 0; db < 4; db++) {
                uint32_t vh[4];
                ldm4t(vh, tb + KTB + ks * (16 * AST) + vfrag + db * 32);
#pragma unroll
                for (int half = 0; half < 2; half++) {
                    int o = db * 2 + half, off = half * 2;
                    mma_fp16(acc[o], pah, &vh[off]);
                    mma_fp16(acc[o], pal, &vh[off]);
                }
            }
        }
    }

    // epilogue: normalize + write single fp16
    float inv0 = 1.f / l0, inv1 = 1.f / l1;
    size_t r0 = qrow0 + wid * 16 + gq;
    size_t base0 = r0 * DMODEL + h * HDIM + t4 * 2;
    size_t base1 = (r0 + 8) * DMODEL + h * HDIM + t4 * 2;
#pragma unroll
    for (int o = 0; o < 8; o++) {
        __half2 p0 = __halves2half2(__float2half_rn(acc[o][0] * inv0),
                                    __float2half_rn(acc[o][1] * inv0));
        __half2 p1 = __halves2half2(__float2half_rn(acc[o][2] * inv1),
                                    __float2half_rn(acc[o][3] * inv1));
        *(uint32_t*)(g_oh + base0 + o * 8) = *(uint32_t*)&p0;
        *(uint32_t*)(g_oh + base1 + o * 8) = *(uint32_t*)&p1;
    }
}

// ---------------------------------------------------------------------------
extern "C" void kernel_launch(void* const* d_in, const int* in_sizes, int n_in,
                              void* d_out, int out_size)
{
    const float* x    = (const float*)d_in[0];
    const float* wqkv = (const float*)d_in[1];
    const float* bqkv = (const float*)d_in[2];
    const float* wo   = (const float*)d_in[3];
    const float* bo   = (const float*)d_in[4];
    float* out = (float*)d_out;

    __half *qkvh, *qkvl, *xh, *wq, *wo16, *oh;
    cudaGetSymbolAddress((void**)&qkvh, g_qkvh);
    cudaGetSymbolAddress((void**)&qkvl, g_qkvl);
    cudaGetSymbolAddress((void**)&xh, g_xh);
    cudaGetSymbolAddress((void**)&wq, g_wq);
    cudaGetSymbolAddress((void**)&wo16, g_wo);
    cudaGetSymbolAddress((void**)&oh, g_oh);

    cudaFuncSetAttribute(gemm_mma<0>, cudaFuncAttributeMaxDynamicSharedMemorySize, SMEM_G);
    cudaFuncSetAttribute(gemm_mma<1>, cudaFuncAttributeMaxDynamicSharedMemorySize, SMEM_G);
    cudaFuncSetAttribute(attn_mma,    cudaFuncAttributeMaxDynamicSharedMemorySize, SMEM_A);

    conv_x<<<MROWS, 256>>>(x);
    dim3 wb(32, 8);
    wconv<<<dim3(DQKV / 32, DMODEL / 32), wb>>>(wqkv, wq, DMODEL, DQKV);
    wconv<<<dim3(DMODEL / 32, DMODEL / 32), wb>>>(wo, wo16, DMODEL, DMODEL);

    // 1) QKV projection (single fp16) -> fp16 hi/lo qkv
    gemm_mma<1><<<dim3(DQKV / 128, MROWS / 128), 256, SMEM_G>>>(
        xh, wq, bqkv, nullptr, qkvh, qkvl, DQKV);

    // 2) attention (Q,P hi/lo; K,V single) -> single fp16
    attn_mma<<<1024, 256, SMEM_A>>>(qkvh, qkvl);

    // 3) output projection (single fp16) -> fp32 out
    gemm_mma<0><<<dim3(DMODEL / 128, MROWS / 128), 256, SMEM_G>>>(
        oh, wo16, bo, out, nullptr, nullptr, DMODEL);
}

// round 8
// speedup vs baseline: 6.6813x; 1.1236x over previous
#include <cuda_runtime.h>
#include <cuda_bf16.h>
#include <cuda_fp16.h>
#include <cstdint>
#include <math.h>

#define BATCH   2
#define SEQ     8192
#define DMODEL  1024
#define NHEADS  16
#define HDIM    64
#define SEGLEN  2048
#define LSEG    1024
#define MROWS   8192
#define DQKV    3072

// ---------------- device scratch ----------------
__device__ __half  g_qkvh[(size_t)MROWS * DQKV];   // qkv hi (fp16)
__device__ __half  g_qkvl[(size_t)MROWS * DQKV];   // qkv lo (only Q part written/read)
__device__ __half  g_xh [(size_t)MROWS * DMODEL];
__device__ __half  g_wq [(size_t)DQKV * DMODEL];
__device__ __half  g_wo [(size_t)DMODEL * DMODEL];
__device__ __half  g_oh [(size_t)MROWS * DMODEL];

// ---------------- PTX helpers ----------------
__device__ __forceinline__ uint32_t smem_u32(const void* p) {
    uint32_t a;
    asm("{ .reg .u64 t; cvta.to.shared.u64 t, %1; cvt.u32.u64 %0, t; }" : "=r"(a) : "l"(p));
    return a;
}
__device__ __forceinline__ void cp16(uint32_t s, const void* g) {
    asm volatile("cp.async.cg.shared.global [%0], [%1], 16;" :: "r"(s), "l"(g));
}
__device__ __forceinline__ void cp_commit() { asm volatile("cp.async.commit_group;"); }
__device__ __forceinline__ void cp_wait2()  { asm volatile("cp.async.wait_group 2;"); }
__device__ __forceinline__ void cp_wait1()  { asm volatile("cp.async.wait_group 1;"); }
__device__ __forceinline__ void cp_wait0()  { asm volatile("cp.async.wait_group 0;"); }
__device__ __forceinline__ void ldm4(uint32_t* r, uint32_t addr) {
    asm volatile("ldmatrix.sync.aligned.m8n8.x4.shared.b16 {%0,%1,%2,%3}, [%4];"
        : "=r"(r[0]), "=r"(r[1]), "=r"(r[2]), "=r"(r[3]) : "r"(addr));
}
__device__ __forceinline__ void ldm4t(uint32_t* r, uint32_t addr) {
    asm volatile("ldmatrix.sync.aligned.m8n8.x4.trans.shared.b16 {%0,%1,%2,%3}, [%4];"
        : "=r"(r[0]), "=r"(r[1]), "=r"(r[2]), "=r"(r[3]) : "r"(addr));
}
__device__ __forceinline__ void mma_fp16(float* c, const uint32_t* a, const uint32_t* b) {
    asm volatile(
        "mma.sync.aligned.m16n8k16.row.col.f32.f16.f16.f32 "
        "{%0,%1,%2,%3}, {%4,%5,%6,%7}, {%8,%9}, {%0,%1,%2,%3};"
        : "+f"(c[0]), "+f"(c[1]), "+f"(c[2]), "+f"(c[3])
        : "r"(a[0]), "r"(a[1]), "r"(a[2]), "r"(a[3]), "r"(b[0]), "r"(b[1]));
}
__device__ __forceinline__ void pack_hl16(float p0, float p1, uint32_t& h, uint32_t& l) {
    __half h0 = __float2half_rn(p0), h1 = __float2half_rn(p1);
    float r0 = p0 - __half2float(h0), r1 = p1 - __half2float(h1);
    __half2 hp = __halves2half2(h0, h1);
    __half2 lp = __halves2half2(__float2half_rn(r0), __float2half_rn(r1));
    h = *(uint32_t*)&hp;
    l = *(uint32_t*)&lp;
}
__device__ __forceinline__ uint32_t pack16(float p0, float p1) {
    __half2 hp = __halves2half2(__float2half_rn(p0), __float2half_rn(p1));
    return *(uint32_t*)&hp;
}

// ---------------------------------------------------------------------------
// convert+gather x -> single fp16
// ---------------------------------------------------------------------------
__global__ void __launch_bounds__(256) conv_x(const float* __restrict__ x) {
    int m = blockIdx.x;
    int b = m >> 12, rem = m & 4095, n = rem >> 10, l = rem & 1023;
    const float* src = x + ((size_t)(b * SEQ + n * SEGLEN + 2 * l)) * DMODEL;
    size_t dst = (size_t)m * DMODEL + threadIdx.x * 4;
    float4 v = *(const float4*)(src + threadIdx.x * 4);
    uint2 o;
    o.x = pack16(v.x, v.y);
    o.y = pack16(v.z, v.w);
    *(uint2*)(g_xh + dst) = o;
}

__global__ void __launch_bounds__(256)
wconv(const float* __restrict__ W, __half* __restrict__ Bt, int K, int N) {
    __shared__ float t[32][33];
    int n0 = blockIdx.x * 32, k0 = blockIdx.y * 32;
    int tx = threadIdx.x, ty = threadIdx.y;
    for (int i = ty; i < 32; i += 8)
        t[i][tx] = W[(size_t)(k0 + i) * N + n0 + tx];
    __syncthreads();
    for (int i = ty; i < 32; i += 8)
        Bt[(size_t)(n0 + i) * K + k0 + tx] = __float2half_rn(t[tx][i]);
}

// ---------------------------------------------------------------------------
// single-product fp16 GEMM, 4-stage cp.async pipeline.
// OUT=0: fp32 C.  OUT=1: fp16 hi (+ lo only for bn < DMODEL, i.e. Q columns).
// ---------------------------------------------------------------------------
#define TS       10240
#define STAGE_G  (2 * TS)
#define SMEM_G   (4 * STAGE_G)

template<int OUT>
__global__ void __launch_bounds__(256)
gemm_mma(const __half* __restrict__ A, const __half* __restrict__ B,
         const float* __restrict__ bias, float* __restrict__ C,
         __half* __restrict__ Ch, __half* __restrict__ Cl, int Ncols)
{
    extern __shared__ char dsm[];
    __shared__ float biass[128];

    const int tid  = threadIdx.x;
    const int wid  = tid >> 5, lane = tid & 31;
    const int wm   = wid & 3, wn = wid >> 2;
    const int bn   = blockIdx.x * 128, bm = blockIdx.y * 128;
    const uint32_t sb = smem_u32(dsm);

    if (tid < 128) biass[tid] = bias[bn + tid];

    const __half* srcs[2] = { A + (size_t)bm * DMODEL, B + (size_t)bn * DMODEL };

    int crow[4], ckc[4], ctile[4];
#pragma unroll
    for (int i = 0; i < 4; i++) {
        int c = tid + i * 256;
        ctile[i] = c >> 9;
        crow[i]  = (c >> 2) & 127;
        ckc[i]   = (c & 3) * 8;
    }

    uint32_t aRow[2], bRow[4];
#pragma unroll
    for (int mt = 0; mt < 2; mt++)
        aRow[mt] = (uint32_t)((wm * 32 + mt * 16 + (lane & 15)) * 80 + (lane >> 4) * 16);
#pragma unroll
    for (int nt2 = 0; nt2 < 4; nt2++)
        bRow[nt2] = (uint32_t)((wn * 64 + nt2 * 16 + (lane & 7) + ((lane >> 4) << 3)) * 80
                               + ((lane >> 3) & 1) * 16);

    float acc[2][8][4];
#pragma unroll
    for (int mt = 0; mt < 2; mt++)
#pragma unroll
        for (int nt = 0; nt < 8; nt++)
#pragma unroll
            for (int j = 0; j < 4; j++) acc[mt][nt][j] = 0.f;

    const int NK = DMODEL / 32;
#pragma unroll
    for (int s = 0; s < 3; s++) {
        uint32_t sbase = sb + s * STAGE_G;
        int k0 = s * 32;
#pragma unroll
        for (int i = 0; i < 4; i++)
            cp16(sbase + ctile[i] * TS + (crow[i] * 40 + ckc[i]) * 2,
                 srcs[ctile[i]] + (size_t)crow[i] * DMODEL + k0 + ckc[i]);
        cp_commit();
    }

#pragma unroll 1
    for (int kc = 0; kc < NK; kc++) {
        cp_wait2();
        __syncthreads();
        if (kc + 3 < NK) {
            uint32_t sbase = sb + ((kc + 3) & 3) * STAGE_G;
            int k0 = (kc + 3) * 32;
#pragma unroll
            for (int i = 0; i < 4; i++)
                cp16(sbase + ctile[i] * TS + (crow[i] * 40 + ckc[i]) * 2,
                     srcs[ctile[i]] + (size_t)crow[i] * DMODEL + k0 + ckc[i]);
        }
        cp_commit();

        uint32_t tb = sb + (kc & 3) * STAGE_G;
#pragma unroll
        for (int ks = 0; ks < 2; ks++) {
            uint32_t ko = ks * 32;
            uint32_t ah[2][4], bb[4][4];
#pragma unroll
            for (int mt = 0; mt < 2; mt++)
                ldm4(ah[mt], tb + aRow[mt] + ko);
#pragma unroll
            for (int nt2 = 0; nt2 < 4; nt2++)
                ldm4(bb[nt2], tb + TS + bRow[nt2] + ko);
#pragma unroll
            for (int mt = 0; mt < 2; mt++)
#pragma unroll
                for (int nt = 0; nt < 8; nt++)
                    mma_fp16(acc[mt][nt], ah[mt], &bb[nt >> 1][(nt & 1) * 2]);
        }
    }

    const int gq = lane >> 2, t4 = lane & 3;
    const bool wantLo = (OUT == 1) && (bn < DMODEL);   // lo only for Q columns
#pragma unroll
    for (int mt = 0; mt < 2; mt++) {
        int row0 = bm + wm * 32 + mt * 16 + gq;
#pragma unroll
        for (int nt = 0; nt < 8; nt++) {
            int colL = wn * 64 + nt * 8 + t4 * 2;
            int col  = bn + colL;
            float v00 = acc[mt][nt][0] + biass[colL];
            float v01 = acc[mt][nt][1] + biass[colL + 1];
            float v10 = acc[mt][nt][2] + biass[colL];
            float v11 = acc[mt][nt][3] + biass[colL + 1];
            if (OUT == 0) {
                *(float2*)(C + (size_t)row0 * Ncols + col) = make_float2(v00, v01);
                *(float2*)(C + (size_t)(row0 + 8) * Ncols + col) = make_float2(v10, v11);
            } else {
                uint32_t h, l;
                pack_hl16(v00, v01, h, l);
                *(uint32_t*)(Ch + (size_t)row0 * Ncols + col) = h;
                if (wantLo) *(uint32_t*)(Cl + (size_t)row0 * Ncols + col) = l;
                pack_hl16(v10, v11, h, l);
                *(uint32_t*)(Ch + (size_t)(row0 + 8) * Ncols + col) = h;
                if (wantLo) *(uint32_t*)(Cl + (size_t)(row0 + 8) * Ncols + col) = l;
            }
        }
    }
}

// ---------------------------------------------------------------------------
// Flash attention: Q fp16 hi/lo (2-product QK); P single fp16; K,V single fp16.
// 3-stage KV pipeline, 1 sync per tile.
// ---------------------------------------------------------------------------
#define AST     144
#define KTB     (64 * AST)
#define STG_A   (2 * KTB)
#define SMEM_A  (3 * STG_A)

__global__ void __launch_bounds__(256, 2)
attn_mma(const __half* __restrict__ Qh, const __half* __restrict__ Ql)
{
    extern __shared__ char dsm[];
    const uint32_t sb = smem_u32(dsm);

    const int tid  = threadIdx.x;
    const int wid  = tid >> 5, lane = tid & 31;
    const int gq = lane >> 2, t4 = lane & 3;
    const int qt = blockIdx.x & 7;
    const int h  = (blockIdx.x >> 3) & 15;
    const int bn = blockIdx.x >> 7;
    const size_t rowbase = (size_t)bn * LSEG;
    const size_t qrow0 = rowbase + qt * 128;

    {
#pragma unroll
        for (int i = 0; i < 8; i++) {
            int idx = tid + i * 256;
            int t   = idx >> 10;
            int r   = (idx >> 3) & 127;
            int c   = idx & 7;
            const __half* src = (t == 0 ? Qh : Ql)
                + (qrow0 + r) * DQKV + h * HDIM + c * 8;
            cp16(sb + t * (128 * AST) + r * AST + c * 16, src);
        }
        cp_commit();
        cp_wait0();
        __syncthreads();
    }
    uint32_t qah[4][4], qal[4][4];
    {
        uint32_t qbase = sb + (wid * 16 + (lane & 15)) * AST + (lane >> 4) * 16;
#pragma unroll
        for (int ks = 0; ks < 4; ks++) {
            ldm4(qah[ks], qbase + ks * 32);
            ldm4(qal[ks], qbase + 128 * AST + ks * 32);
        }
    }
    __syncthreads();

    int crow[4], cch[4], ctl[4];
#pragma unroll
    for (int i = 0; i < 4; i++) {
        int idx = tid + i * 256;
        ctl[i]  = idx >> 9;
        crow[i] = (idx >> 3) & 63;
        cch[i]  = idx & 7;
    }
    const __half* kvsrc[2] = {
        Qh + rowbase * DQKV + DMODEL     + h * HDIM,
        Qh + rowbase * DQKV + 2 * DMODEL + h * HDIM };

    const uint32_t kfrag = ((lane & 7) + ((lane >> 4) << 3)) * AST + ((lane >> 3) & 1) * 16;
    const uint32_t vfrag = ((lane & 7) + ((lane >> 3) & 1) * 8) * AST + (lane >> 4) * 16;

    float acc[8][4];
#pragma unroll
    for (int o = 0; o < 8; o++)
#pragma unroll
        for (int j = 0; j < 4; j++) acc[o][j] = 0.f;
    float m0 = -1e30f, m1 = -1e30f, l0 = 0.f, l1 = 0.f;

    const int NT = LSEG / 64;
#pragma unroll
    for (int s = 0; s < 2; s++) {
        uint32_t sbase = sb + s * STG_A;
        size_t roff = (size_t)s * 64;
#pragma unroll
        for (int i = 0; i < 4; i++)
            cp16(sbase + ctl[i] * KTB + crow[i] * AST + cch[i] * 16,
                 kvsrc[ctl[i]] + (roff + crow[i]) * DQKV + cch[i] * 8);
        cp_commit();
    }

#pragma unroll 1
    for (int kt = 0; kt < NT; kt++) {
        if (kt < NT - 1) cp_wait1(); else cp_wait0();
        __syncthreads();
        if (kt + 2 < NT) {
            uint32_t sbase = sb + ((kt + 2) % 3) * STG_A;
            size_t roff = (size_t)(kt + 2) * 64;
#pragma unroll
            for (int i = 0; i < 4; i++)
                cp16(sbase + ctl[i] * KTB + crow[i] * AST + cch[i] * 16,
                     kvsrc[ctl[i]] + (roff + crow[i]) * DQKV + cch[i] * 8);
            cp_commit();
        }

        const uint32_t tb = sb + (kt % 3) * STG_A;

        float sacc[8][4];
#pragma unroll
        for (int o = 0; o < 8; o++)
#pragma unroll
            for (int j = 0; j < 4; j++) sacc[o][j] = 0.f;

#pragma unroll
        for (int ks = 0; ks < 4; ks++) {
#pragma unroll
            for (int nt2 = 0; nt2 < 4; nt2++) {
                uint32_t kh[4];
                ldm4(kh, tb + nt2 * (16 * AST) + kfrag + ks * 32);
#pragma unroll
                for (int half = 0; half < 2; half++) {
                    int nt = nt2 * 2 + half, off = half * 2;
                    mma_fp16(sacc[nt], qah[ks], &kh[off]);
                    mma_fp16(sacc[nt], qal[ks], &kh[off]);
                }
            }
        }

        const float SC = 0.125f;
        float mx0 = -1e30f, mx1 = -1e30f;
#pragma unroll
        for (int o = 0; o < 8; o++) {
            sacc[o][0] *= SC; sacc[o][1] *= SC; sacc[o][2] *= SC; sacc[o][3] *= SC;
            mx0 = fmaxf(mx0, fmaxf(sacc[o][0], sacc[o][1]));
            mx1 = fmaxf(mx1, fmaxf(sacc[o][2], sacc[o][3]));
        }
        mx0 = fmaxf(mx0, __shfl_xor_sync(0xffffffffu, mx0, 1));
        mx0 = fmaxf(mx0, __shfl_xor_sync(0xffffffffu, mx0, 2));
        mx1 = fmaxf(mx1, __shfl_xor_sync(0xffffffffu, mx1, 1));
        mx1 = fmaxf(mx1, __shfl_xor_sync(0xffffffffu, mx1, 2));
        float mn0 = fmaxf(m0, mx0), mn1 = fmaxf(m1, mx1);
        float c0 = __expf(m0 - mn0), c1 = __expf(m1 - mn1);
        m0 = mn0; m1 = mn1;
        float rs0 = 0.f, rs1 = 0.f;
#pragma unroll
        for (int o = 0; o < 8; o++) {
            sacc[o][0] = __expf(sacc[o][0] - mn0);
            sacc[o][1] = __expf(sacc[o][1] - mn0);
            sacc[o][2] = __expf(sacc[o][2] - mn1);
            sacc[o][3] = __expf(sacc[o][3] - mn1);
            rs0 += sacc[o][0] + sacc[o][1];
            rs1 += sacc[o][2] + sacc[o][3];
        }
        rs0 += __shfl_xor_sync(0xffffffffu, rs0, 1);
        rs0 += __shfl_xor_sync(0xffffffffu, rs0, 2);
        rs1 += __shfl_xor_sync(0xffffffffu, rs1, 1);
        rs1 += __shfl_xor_sync(0xffffffffu, rs1, 2);
        l0 = l0 * c0 + rs0;
        l1 = l1 * c1 + rs1;
#pragma unroll
        for (int o = 0; o < 8; o++) {
            acc[o][0] *= c0; acc[o][1] *= c0; acc[o][2] *= c1; acc[o][3] *= c1;
        }

        // ---- PV: P single fp16 ----
#pragma unroll
        for (int ks = 0; ks < 4; ks++) {
            uint32_t pa[4];
            pa[0] = pack16(sacc[2 * ks][0],     sacc[2 * ks][1]);
            pa[1] = pack16(sacc[2 * ks][2],     sacc[2 * ks][3]);
            pa[2] = pack16(sacc[2 * ks + 1][0], sacc[2 * ks + 1][1]);
            pa[3] = pack16(sacc[2 * ks + 1][2], sacc[2 * ks + 1][3]);
#pragma unroll
            for (int db = 0; db < 4; db++) {
                uint32_t vh[4];
                ldm4t(vh, tb + KTB + ks * (16 * AST) + vfrag + db * 32);
                mma_fp16(acc[db * 2 + 0], pa, &vh[0]);
                mma_fp16(acc[db * 2 + 1], pa, &vh[2]);
            }
        }
    }

    float inv0 = 1.f / l0, inv1 = 1.f / l1;
    size_t r0 = qrow0 + wid * 16 + gq;
    size_t base0 = r0 * DMODEL + h * HDIM + t4 * 2;
    size_t base1 = (r0 + 8) * DMODEL + h * HDIM + t4 * 2;
#pragma unroll
    for (int o = 0; o < 8; o++) {
        *(uint32_t*)(g_oh + base0 + o * 8) = pack16(acc[o][0] * inv0, acc[o][1] * inv0);
        *(uint32_t*)(g_oh + base1 + o * 8) = pack16(acc[o][2] * inv1, acc[o][3] * inv1);
    }
}

// ---------------------------------------------------------------------------
extern "C" void kernel_launch(void* const* d_in, const int* in_sizes, int n_in,
                              void* d_out, int out_size)
{
    const float* x    = (const float*)d_in[0];
    const float* wqkv = (const float*)d_in[1];
    const float* bqkv = (const float*)d_in[2];
    const float* wo   = (const float*)d_in[3];
    const float* bo   = (const float*)d_in[4];
    float* out = (float*)d_out;

    __half *qkvh, *qkvl, *xh, *wq, *wo16, *oh;
    cudaGetSymbolAddress((void**)&qkvh, g_qkvh);
    cudaGetSymbolAddress((void**)&qkvl, g_qkvl);
    cudaGetSymbolAddress((void**)&xh, g_xh);
    cudaGetSymbolAddress((void**)&wq, g_wq);
    cudaGetSymbolAddress((void**)&wo16, g_wo);
    cudaGetSymbolAddress((void**)&oh, g_oh);

    cudaFuncSetAttribute(gemm_mma<0>, cudaFuncAttributeMaxDynamicSharedMemorySize, SMEM_G);
    cudaFuncSetAttribute(gemm_mma<1>, cudaFuncAttributeMaxDynamicSharedMemorySize, SMEM_G);
    cudaFuncSetAttribute(attn_mma,    cudaFuncAttributeMaxDynamicSharedMemorySize, SMEM_A);

    conv_x<<<MROWS, 256>>>(x);
    dim3 wb(32, 8);
    wconv<<<dim3(DQKV / 32, DMODEL / 32), wb>>>(wqkv, wq, DMODEL, DQKV);
    wconv<<<dim3(DMODEL / 32, DMODEL / 32), wb>>>(wo, wo16, DMODEL, DMODEL);

    gemm_mma<1><<<dim3(DQKV / 128, MROWS / 128), 256, SMEM_G>>>(
        xh, wq, bqkv, nullptr, qkvh, qkvl, DQKV);

    attn_mma<<<1024, 256, SMEM_A>>>(qkvh, qkvl);

    gemm_mma<0><<<dim3(DMODEL / 128, MROWS / 128), 256, SMEM_G>>>(
        oh, wo16, bo, out, nullptr, nullptr, DMODEL);
}